// round 13
// baseline (speedup 1.0000x reference)
#include <cuda_runtime.h>
#include <cuda_bf16.h>
#include <math.h>
#include <stdint.h>

#define B_ 2
#define T_ 2048
#define C_ 2048
#define H_ 16
#define D_ 128
#define M_ 4096
#define NQKV_ 6144
#define K_ 2048
#define NCHUNK 32      /* K_/64 */

// ---------------- scratch (device globals: allocation-free) ----------------
__device__ float g_qkv[(size_t)M_*NQKV_];
__device__ __nv_bfloat16 g_xh[(size_t)M_*C_],    g_xl[(size_t)M_*C_];
__device__ __nv_bfloat16 g_wh[(size_t)NQKV_*C_], g_wl[(size_t)NQKV_*C_];
__device__ __nv_bfloat16 g_oh[(size_t)C_*C_],    g_ol[(size_t)C_*C_];
__device__ __nv_bfloat16 g_ah[(size_t)M_*C_],    g_al[(size_t)M_*C_];  // attn out (ref layout)
__device__ __nv_bfloat16 g_qh[(size_t)B_*H_*T_*D_], g_ql[(size_t)B_*H_*T_*D_];
__device__ __nv_bfloat16 g_kh[(size_t)B_*H_*T_*D_], g_kl[(size_t)B_*H_*T_*D_];
__device__ __nv_bfloat16 g_vth[(size_t)B_*H_*D_*T_], g_vtl[(size_t)B_*H_*D_*T_]; // [B,H,D,T]

extern __shared__ __align__(16) char dyn_smem[];

// ---------------- sm_80-class primitives (legal on plain sm_103) -----------
__device__ __forceinline__ uint32_t smem_u32(const void* p) {
    uint32_t a;
    asm("{ .reg .u64 t; cvta.to.shared.u64 t, %1; cvt.u32.u64 %0, t; }"
        : "=r"(a) : "l"(p));
    return a;
}
__device__ __forceinline__ void cp16(uint32_t dst, const void* src) {
    asm volatile("cp.async.cg.shared.global [%0], [%1], 16;"
                 :: "r"(dst), "l"(src) : "memory");
}
__device__ __forceinline__ void cp_commit() {
    asm volatile("cp.async.commit_group;" ::: "memory");
}
__device__ __forceinline__ void cp_wait0() {
    asm volatile("cp.async.wait_group 0;" ::: "memory");
}
__device__ __forceinline__ void cp_wait1() {
    asm volatile("cp.async.wait_group 1;" ::: "memory");
}
__device__ __forceinline__ void ldsm_x4(uint32_t* r, uint32_t addr) {
    asm volatile("ldmatrix.sync.aligned.m8n8.x4.shared.b16 {%0,%1,%2,%3}, [%4];"
                 : "=r"(r[0]), "=r"(r[1]), "=r"(r[2]), "=r"(r[3]) : "r"(addr));
}
__device__ __forceinline__ void mma16816(float* c, const uint32_t* a, const uint32_t* b) {
    asm volatile(
        "mma.sync.aligned.m16n8k16.row.col.f32.bf16.bf16.f32 "
        "{%0,%1,%2,%3}, {%4,%5,%6,%7}, {%8,%9}, {%0,%1,%2,%3};"
        : "+f"(c[0]), "+f"(c[1]), "+f"(c[2]), "+f"(c[3])
        : "r"(a[0]), "r"(a[1]), "r"(a[2]), "r"(a[3]), "r"(b[0]), "r"(b[1]));
}
// SW128 swizzled address inside a [rows][64 bf16] tile (128B rows)
__device__ __forceinline__ uint32_t swz(uint32_t tile_base, int row, int col2 /*bytes*/) {
    return tile_base + ((uint32_t)row << 7) + ((uint32_t)col2 ^ (((uint32_t)row & 7u) << 4));
}
__device__ __forceinline__ uint32_t pack_bf2(__nv_bfloat16 lo, __nv_bfloat16 hi) {
    return (uint32_t)__bfloat16_as_ushort(lo) | ((uint32_t)__bfloat16_as_ushort(hi) << 16);
}
__device__ __forceinline__ void bsplit(float f, __nv_bfloat16& h, __nv_bfloat16& l) {
    h = __float2bfloat16_rn(f);
    l = __float2bfloat16_rn(f - __bfloat162float(h));
}

// tile loaders: [64 rows][64 bf16] and [128 rows][64 bf16], SW128 swizzled
__device__ __forceinline__ void tile64_async(uint32_t dst, const __nv_bfloat16* src,
                                             size_t pitch, int tid)
{
#pragma unroll
    for (int u = 0; u < 2; ++u) {
        const int c = tid*2 + u;
        const int row = c >> 3, seg = (c & 7) * 16;
        uint32_t o = (uint32_t)(row*128 + seg);
        o ^= ((o >> 3) & 0x70);
        cp16(dst + o, (const char*)(src + (size_t)row*pitch) + seg);
    }
}
__device__ __forceinline__ void tile128_async(uint32_t dst, const __nv_bfloat16* src,
                                              size_t pitch, int tid)
{
#pragma unroll
    for (int u = 0; u < 4; ++u) {
        const int c = tid*4 + u;
        const int row = c >> 3, seg = (c & 7) * 16;
        uint32_t o = (uint32_t)(row*128 + seg);
        o ^= ((o >> 3) & 0x70);
        cp16(dst + o, (const char*)(src + (size_t)row*pitch) + seg);
    }
}

// ---------------------------------------------------------------------------
// fp32 -> (bf16 hi, bf16 lo) split, 4 elements per thread.
// ---------------------------------------------------------------------------
__global__ void __launch_bounds__(256)
split_bf16(const float* __restrict__ src, __nv_bfloat16* __restrict__ hi,
           __nv_bfloat16* __restrict__ lo, int n4)
{
    const int i = blockIdx.x*256 + threadIdx.x;
    if (i >= n4) return;
    const float4 v = ((const float4*)src)[i];
    float f[4] = {v.x, v.y, v.z, v.w};
    __nv_bfloat16 h[4], l[4];
#pragma unroll
    for (int j = 0; j < 4; ++j) {
        h[j] = __float2bfloat16_rn(f[j]);
        l[j] = __float2bfloat16_rn(f[j] - __bfloat162float(h[j]));
    }
    ((__nv_bfloat162*)hi)[i*2+0] = __halves2bfloat162(h[0], h[1]);
    ((__nv_bfloat162*)hi)[i*2+1] = __halves2bfloat162(h[2], h[3]);
    ((__nv_bfloat162*)lo)[i*2+0] = __halves2bfloat162(l[0], l[1]);
    ((__nv_bfloat162*)lo)[i*2+1] = __halves2bfloat162(l[2], l[3]);
}

// ---------------------------------------------------------------------------
// HMMA bf16 3-split NT GEMM. CTA tile 64(M)x128(N), BK=64, 2-stage double
// buffer, 2 CTAs/SM (decorrelates barriers -> fills tensor-pipe idle).
// 8 warps: 2(m) x 4(n), warp tile 32x32.
// ---------------------------------------------------------------------------
#define GSTG 49152u   /* bytes per stage: Ah 8K, Al 8K, Bh 16K, Bl 16K */
#define GOFF_AH 0u
#define GOFF_AL 8192u
#define GOFF_BH 16384u
#define GOFF_BL 32768u
#define TC_SMEM (2*49152)   /* 96 KB */

__global__ void __launch_bounds__(256, 2)
tc_gemm(const __nv_bfloat16* __restrict__ Ah, const __nv_bfloat16* __restrict__ Al,
        const __nv_bfloat16* __restrict__ Bh, const __nv_bfloat16* __restrict__ Bl,
        float* __restrict__ Cout, int N)
{
    const uint32_t sbase = smem_u32(dyn_smem);
    const int tid = threadIdx.x, wid = tid >> 5, lane = tid & 31;
    const int wy = wid >> 2, wx = wid & 3;          // 2 x 4 warp grid
    const int m0 = blockIdx.y * 64, n0 = blockIdx.x * 128;
    const int r = lane & 7, g = lane >> 3;

    float acc[2][4][4];
#pragma unroll
    for (int i = 0; i < 2; ++i)
#pragma unroll
        for (int j = 0; j < 4; ++j)
#pragma unroll
            for (int e = 0; e < 4; ++e) acc[i][j][e] = 0.0f;

    // prologue: chunks 0,1 -> stages 0,1
#pragma unroll
    for (int p = 0; p < 2; ++p) {
        const uint32_t st = sbase + p*GSTG;
        tile64_async (st + GOFF_AH, Ah + (size_t)m0*K_ + p*64, K_, tid);
        tile64_async (st + GOFF_AL, Al + (size_t)m0*K_ + p*64, K_, tid);
        tile128_async(st + GOFF_BH, Bh + (size_t)n0*K_ + p*64, K_, tid);
        tile128_async(st + GOFF_BL, Bl + (size_t)n0*K_ + p*64, K_, tid);
        cp_commit();
    }

    for (int chunk = 0; chunk < NCHUNK; ++chunk) {
        const uint32_t st = sbase + (uint32_t)(chunk & 1)*GSTG;
        if (chunk == NCHUNK-1) cp_wait0(); else cp_wait1();
        __syncthreads();                       // chunk data visible
#pragma unroll
        for (int ks = 0; ks < 4; ++ks) {
            uint32_t ah[2][4], alr[2][4], bh[4][2], blr[4][2];
            const int colA = ks*32 + (g>>1)*16;
            const int colB = ks*32 + (g&1)*16;
#pragma unroll
            for (int i = 0; i < 2; ++i) {
                const int row = wy*32 + i*16 + r + (g&1)*8;
                ldsm_x4(ah[i],  swz(st + GOFF_AH, row, colA));
                ldsm_x4(alr[i], swz(st + GOFF_AL, row, colA));
            }
#pragma unroll
            for (int jj = 0; jj < 2; ++jj) {
                const int row = wx*32 + jj*16 + r + (g>>1)*8;
                uint32_t t[4];
                ldsm_x4(t, swz(st + GOFF_BH, row, colB));
                bh[jj*2][0]=t[0]; bh[jj*2][1]=t[1];
                bh[jj*2+1][0]=t[2]; bh[jj*2+1][1]=t[3];
                ldsm_x4(t, swz(st + GOFF_BL, row, colB));
                blr[jj*2][0]=t[0]; blr[jj*2][1]=t[1];
                blr[jj*2+1][0]=t[2]; blr[jj*2+1][1]=t[3];
            }
#pragma unroll
            for (int i = 0; i < 2; ++i)
#pragma unroll
                for (int j = 0; j < 4; ++j)
                    mma16816(acc[i][j], ah[i],  bh[j]);
#pragma unroll
            for (int i = 0; i < 2; ++i)
#pragma unroll
                for (int j = 0; j < 4; ++j)
                    mma16816(acc[i][j], ah[i],  blr[j]);
#pragma unroll
            for (int i = 0; i < 2; ++i)
#pragma unroll
                for (int j = 0; j < 4; ++j)
                    mma16816(acc[i][j], alr[i], bh[j]);
        }
        if (chunk + 2 < NCHUNK) {
            __syncthreads();                   // all warps done reading st
            const int k0n = (chunk + 2) * 64;
            tile64_async (st + GOFF_AH, Ah + (size_t)m0*K_ + k0n, K_, tid);
            tile64_async (st + GOFF_AL, Al + (size_t)m0*K_ + k0n, K_, tid);
            tile128_async(st + GOFF_BH, Bh + (size_t)n0*K_ + k0n, K_, tid);
            tile128_async(st + GOFF_BL, Bl + (size_t)n0*K_ + k0n, K_, tid);
            cp_commit();
        }
    }
#pragma unroll
    for (int i = 0; i < 2; ++i) {
        const int rm = m0 + wy*32 + i*16 + (lane >> 2);
#pragma unroll
        for (int j = 0; j < 4; ++j) {
            const int cn = n0 + wx*32 + j*8 + (lane & 3)*2;
            *(float2*)&Cout[(size_t)rm*N + cn]     = make_float2(acc[i][j][0], acc[i][j][1]);
            *(float2*)&Cout[(size_t)(rm+8)*N + cn] = make_float2(acc[i][j][2], acc[i][j][3]);
        }
    }
}

// ---------------------------------------------------------------------------
// RoPE + reorganize -> bf16 splits (unchanged).
// ---------------------------------------------------------------------------
__global__ void rope_reorg()
{
    const int idx = blockIdx.x * 256 + threadIdx.x;
    const int t4 = idx & 511;
    const int i  = (idx >> 9) & 63;
    const int h  = (idx >> 15) & (H_ - 1);
    const int b  = idx >> 19;
    const int bh = b*H_ + h;
    const int col = h*D_ + i;

    const float mlt = (float)(-9.210340371976184 / 128.0);
    const float div = expf((float)(2*i) * mlt);

#pragma unroll
    for (int u = 0; u < 4; ++u) {
        const int t = t4*4 + u;
        const size_t row = (size_t)(b*T_ + t) * NQKV_;
        const float q1 = g_qkv[row + 0*C_ + col];
        const float q2 = g_qkv[row + 0*C_ + col + 64];
        const float k1 = g_qkv[row + 1*C_ + col];
        const float k2 = g_qkv[row + 1*C_ + col + 64];
        const float v1 = g_qkv[row + 2*C_ + col];
        const float v2 = g_qkv[row + 2*C_ + col + 64];

        float s, c;
        sincosf((float)t * div, &s, &c);
        const float qa = q1*c - q2*s, qb2 = q2*c + q1*s;
        const float ka = k1*c - k2*s, kb2 = k2*c + k1*s;

        const size_t off = ((size_t)bh * T_ + t) * D_ + i;
        __nv_bfloat16 hh, ll;
        bsplit(qa,  hh, ll); g_qh[off]      = hh; g_ql[off]      = ll;
        bsplit(qb2, hh, ll); g_qh[off + 64] = hh; g_ql[off + 64] = ll;
        bsplit(ka,  hh, ll); g_kh[off]      = hh; g_kl[off]      = ll;
        bsplit(kb2, hh, ll); g_kh[off + 64] = hh; g_kl[off + 64] = ll;
        const size_t koff = ((size_t)bh * D_ + i) * T_ + t;
        bsplit(v1, hh, ll); g_vth[koff]          = hh; g_vtl[koff]          = ll;
        bsplit(v2, hh, ll); g_vth[koff + 64*T_]  = hh; g_vtl[koff + 64*T_]  = ll;
    }
}

// ---------------------------------------------------------------------------
// HMMA causal flash attention (unchanged from R12, passed).
// ---------------------------------------------------------------------------
#define AQ_OFF   0u
#define AKV_OFF(buf) (32768u + (buf)*65536u)
#define ASS_OFF  163840u
#define APH_OFF  181248u
#define APL_OFF  189440u
#define AML_OFF  197632u
#define ATT_SMEM (197632 + 768)

__global__ void __launch_bounds__(256, 1)
attn_kernel()
{
    const uint32_t sb = smem_u32(dyn_smem);
    float* Ss  = (float*)(dyn_smem + ASS_OFF);
    float* m_s = (float*)(dyn_smem + AML_OFF);
    float* l_s = m_s + 64;
    float* sc_s = l_s + 64;

    const int tid = threadIdx.x, wid = tid >> 5, lane = tid & 31;
    const int r = lane & 7, g = lane >> 3;
    const int wq = wid >> 1, wk = wid & 1;
    const int qt = (gridDim.x - 1) - blockIdx.x;
    const int h = blockIdx.y, b = blockIdx.z;
    const size_t hoff  = (size_t)(b*H_ + h) * T_ * D_;
    const size_t hofft = (size_t)(b*H_ + h) * D_ * T_;
    const int q0 = qt * 64;

    tile64_async(sb + AQ_OFF + 0,     g_qh + hoff + (size_t)q0*D_,      D_, tid);
    tile64_async(sb + AQ_OFF + 8192,  g_qh + hoff + (size_t)q0*D_ + 64, D_, tid);
    tile64_async(sb + AQ_OFF + 16384, g_ql + hoff + (size_t)q0*D_,      D_, tid);
    tile64_async(sb + AQ_OFF + 24576, g_ql + hoff + (size_t)q0*D_ + 64, D_, tid);
    {
        const uint32_t kv = sb + AKV_OFF(0);
        tile64_async (kv + 0,     g_kh + hoff, D_, tid);
        tile64_async (kv + 8192,  g_kh + hoff + 64, D_, tid);
        tile64_async (kv + 16384, g_kl + hoff, D_, tid);
        tile64_async (kv + 24576, g_kl + hoff + 64, D_, tid);
        tile128_async(kv + 32768, g_vth + hofft, T_, tid);
        tile128_async(kv + 49152, g_vtl + hofft, T_, tid);
    }
    cp_commit(); cp_wait0();
    if (tid < 64) { m_s[tid] = -INFINITY; l_s[tid] = 0.0f; }
    __syncthreads();

    float acc[8][4];
#pragma unroll
    for (int j = 0; j < 8; ++j)
#pragma unroll
        for (int e = 0; e < 4; ++e) acc[j][e] = 0.0f;

    const float scl = 0.08838834764831845f;
    const int sr = tid >> 2, sq = tid & 3;

    for (int kt = 0; kt <= qt; ++kt) {
        const int buf = kt & 1;
        if (kt < qt) {
            const int k0n = (kt + 1) * 64;
            const uint32_t kv = sb + AKV_OFF(buf^1);
            tile64_async (kv + 0,     g_kh + hoff + (size_t)k0n*D_, D_, tid);
            tile64_async (kv + 8192,  g_kh + hoff + (size_t)k0n*D_ + 64, D_, tid);
            tile64_async (kv + 16384, g_kl + hoff + (size_t)k0n*D_, D_, tid);
            tile64_async (kv + 24576, g_kl + hoff + (size_t)k0n*D_ + 64, D_, tid);
            tile128_async(kv + 32768, g_vth + hofft + k0n, T_, tid);
            tile128_async(kv + 49152, g_vtl + hofft + k0n, T_, tid);
            cp_commit();
        }
        const uint32_t sQH = sb + AQ_OFF, sQL = sb + AQ_OFF + 16384;
        const uint32_t sKH = sb + AKV_OFF(buf), sKL = sKH + 16384;
        const uint32_t sVH = sb + AKV_OFF(buf) + 32768, sVL = sVH + 16384;

        // ---- S = Q K^T (3-split) ----
        {
            float s[4][4];
#pragma unroll
            for (int j = 0; j < 4; ++j)
#pragma unroll
                for (int e = 0; e < 4; ++e) s[j][e] = 0.0f;
#pragma unroll
            for (int ks = 0; ks < 8; ++ks) {
                const uint32_t subo = (uint32_t)(ks >> 2) * 8192u;
                const int colA = (ks & 3)*32 + (g>>1)*16;
                const int colB = (ks & 3)*32 + (g&1)*16;
                uint32_t ah[4], al[4], bh[4][2], bl[4][2];
                const int rowA = wq*16 + r + (g&1)*8;
                ldsm_x4(ah, swz(sQH + subo, rowA, colA));
                ldsm_x4(al, swz(sQL + subo, rowA, colA));
#pragma unroll
                for (int jj = 0; jj < 2; ++jj) {
                    const int rowB = wk*32 + jj*16 + r + (g>>1)*8;
                    uint32_t t[4];
                    ldsm_x4(t, swz(sKH + subo, rowB, colB));
                    bh[jj*2][0]=t[0]; bh[jj*2][1]=t[1];
                    bh[jj*2+1][0]=t[2]; bh[jj*2+1][1]=t[3];
                    ldsm_x4(t, swz(sKL + subo, rowB, colB));
                    bl[jj*2][0]=t[0]; bl[jj*2][1]=t[1];
                    bl[jj*2+1][0]=t[2]; bl[jj*2+1][1]=t[3];
                }
#pragma unroll
                for (int j = 0; j < 4; ++j) mma16816(s[j], ah, bh[j]);
#pragma unroll
                for (int j = 0; j < 4; ++j) mma16816(s[j], ah, bl[j]);
#pragma unroll
                for (int j = 0; j < 4; ++j) mma16816(s[j], al, bh[j]);
            }
#pragma unroll
            for (int j = 0; j < 4; ++j) {
                const int row0 = wq*16 + (lane >> 2);
                const int cc = wk*32 + j*8 + (lane & 3)*2;
                *(float2*)&Ss[row0*68 + cc]     = make_float2(s[j][0]*scl, s[j][1]*scl);
                *(float2*)&Ss[(row0+8)*68 + cc] = make_float2(s[j][2]*scl, s[j][3]*scl);
            }
        }
        __syncthreads();
        // ---- softmax (fp32) + write P splits ----
        {
            const int k0 = kt * 64;
            float* row = Ss + sr*68;
            int kmax = q0 + sr - k0 + 1;
            if (kmax > 64) kmax = 64;
            const float m_old = m_s[sr];
            float mx = m_old;
#pragma unroll
            for (int c0 = 0; c0 < 16; ++c0) {
                const int c = sq*16 + c0;
                if (c < kmax) mx = fmaxf(mx, row[c]);
            }
            mx = fmaxf(mx, __shfl_xor_sync(0xffffffff, mx, 1));
            mx = fmaxf(mx, __shfl_xor_sync(0xffffffff, mx, 2));
            float sum = 0.0f;
#pragma unroll
            for (int cp = 0; cp < 8; ++cp) {
                const int c = sq*16 + cp*2;
                const float p0 = (c   < kmax) ? __expf(row[c]   - mx) : 0.0f;
                const float p1 = (c+1 < kmax) ? __expf(row[c+1] - mx) : 0.0f;
                sum += p0 + p1;
                __nv_bfloat16 h0, l0, h1, l1;
                bsplit(p0, h0, l0); bsplit(p1, h1, l1);
                const int colb = c*2;
                *(uint32_t*)(dyn_smem + swz(APH_OFF, sr, colb)) = pack_bf2(h0, h1);
                *(uint32_t*)(dyn_smem + swz(APL_OFF, sr, colb)) = pack_bf2(l0, l1);
            }
            sum += __shfl_xor_sync(0xffffffff, sum, 1);
            sum += __shfl_xor_sync(0xffffffff, sum, 2);
            if (sq == 0) {
                const float sc = __expf(m_old - mx);
                m_s[sr]  = mx;
                l_s[sr]  = l_s[sr] * sc + sum;
                sc_s[sr] = sc;
            }
        }
        __syncthreads();
        // ---- O = O*sc + P V (3-split) ----
        {
            const int row0 = wq*16 + (lane >> 2);
            const float sc0 = sc_s[row0], sc1 = sc_s[row0 + 8];
#pragma unroll
            for (int j = 0; j < 8; ++j) {
                acc[j][0] *= sc0; acc[j][1] *= sc0;
                acc[j][2] *= sc1; acc[j][3] *= sc1;
            }
#pragma unroll
            for (int ks = 0; ks < 4; ++ks) {
                const int colA = ks*32 + (g>>1)*16;
                const int colB = ks*32 + (g&1)*16;
                uint32_t ah[4], al[4], bh[8][2], bl[8][2];
                const int rowA = wq*16 + r + (g&1)*8;
                ldsm_x4(ah, swz(sb + APH_OFF, rowA, colA));
                ldsm_x4(al, swz(sb + APL_OFF, rowA, colA));
#pragma unroll
                for (int jj = 0; jj < 4; ++jj) {
                    const int rowB = wk*64 + jj*16 + r + (g>>1)*8;
                    uint32_t t[4];
                    ldsm_x4(t, swz(sVH, rowB, colB));
                    bh[jj*2][0]=t[0]; bh[jj*2][1]=t[1];
                    bh[jj*2+1][0]=t[2]; bh[jj*2+1][1]=t[3];
                    ldsm_x4(t, swz(sVL, rowB, colB));
                    bl[jj*2][0]=t[0]; bl[jj*2][1]=t[1];
                    bl[jj*2+1][0]=t[2]; bl[jj*2+1][1]=t[3];
                }
#pragma unroll
                for (int j = 0; j < 8; ++j) mma16816(acc[j], ah, bh[j]);
#pragma unroll
                for (int j = 0; j < 8; ++j) mma16816(acc[j], ah, bl[j]);
#pragma unroll
                for (int j = 0; j < 8; ++j) mma16816(acc[j], al, bh[j]);
            }
        }
        if (kt < qt) cp_wait0();
        __syncthreads();
    }

    // epilogue: normalize + split to bf16 hi/lo, reference layout
    {
        const int row0 = wq*16 + (lane >> 2);
        const float inv0 = 1.0f / l_s[row0];
        const float inv1 = 1.0f / l_s[row0 + 8];
        const int t0 = q0 + row0, t1 = t0 + 8;
        const int rowA = 128*h + (t0 >> 4), rowB2 = 128*h + (t1 >> 4);
        const int cbase0 = ((t0 & 15) << 7), cbase1 = ((t1 & 15) << 7);
#pragma unroll
        for (int j = 0; j < 8; ++j) {
            const int d = wk*64 + j*8 + (lane & 3)*2;
            const size_t i0 = (size_t)(b*T_ + rowA)*C_ + cbase0 + d;
            const size_t i1 = (size_t)(b*T_ + rowB2)*C_ + cbase1 + d;
            __nv_bfloat16 h0, l0, h1, l1;
            bsplit(acc[j][0]*inv0, h0, l0); bsplit(acc[j][1]*inv0, h1, l1);
            *(uint32_t*)&g_ah[i0] = pack_bf2(h0, h1);
            *(uint32_t*)&g_al[i0] = pack_bf2(l0, l1);
            bsplit(acc[j][2]*inv1, h0, l0); bsplit(acc[j][3]*inv1, h1, l1);
            *(uint32_t*)&g_ah[i1] = pack_bf2(h0, h1);
            *(uint32_t*)&g_al[i1] = pack_bf2(l0, l1);
        }
    }
}

// ---------------------------------------------------------------------------
extern "C" void kernel_launch(void* const* d_in, const int* in_sizes, int n_in,
                              void* d_out, int out_size)
{
    const float* x = nullptr; const float* qkv_w = nullptr; const float* out_w = nullptr;
    for (int i = 0; i < n_in; ++i) {
        if      (in_sizes[i] == B_*T_*C_) x     = (const float*)d_in[i];
        else if (in_sizes[i] == 3*C_*C_)  qkv_w = (const float*)d_in[i];
        else if (in_sizes[i] == C_*C_)    out_w = (const float*)d_in[i];
    }
    if (!x)     x     = (const float*)d_in[0];
    if (!qkv_w) qkv_w = (const float*)d_in[1];
    if (!out_w) out_w = (const float*)d_in[2];
    float* out = (float*)d_out;

    float *qkv_ptr;
    __nv_bfloat16 *xh, *xl, *wh, *wl, *oh, *ol, *ah, *al;
    cudaGetSymbolAddress((void**)&qkv_ptr,  g_qkv);
    cudaGetSymbolAddress((void**)&xh, g_xh); cudaGetSymbolAddress((void**)&xl, g_xl);
    cudaGetSymbolAddress((void**)&wh, g_wh); cudaGetSymbolAddress((void**)&wl, g_wl);
    cudaGetSymbolAddress((void**)&oh, g_oh); cudaGetSymbolAddress((void**)&ol, g_ol);
    cudaGetSymbolAddress((void**)&ah, g_ah); cudaGetSymbolAddress((void**)&al, g_al);

    cudaFuncSetAttribute(tc_gemm, cudaFuncAttributeMaxDynamicSharedMemorySize, TC_SMEM);
    cudaFuncSetAttribute(attn_kernel, cudaFuncAttributeMaxDynamicSharedMemorySize, ATT_SMEM);

    // 1) fp32 -> bf16 hi/lo splits
    split_bf16<<<(M_*C_/4 + 255)/256, 256>>>(x, xh, xl, M_*C_/4);
    split_bf16<<<(NQKV_*C_/4 + 255)/256, 256>>>(qkv_w, wh, wl, NQKV_*C_/4);
    split_bf16<<<(C_*C_/4 + 255)/256, 256>>>(out_w, oh, ol, C_*C_/4);
    // 2) QKV projection (HMMA, 2 CTAs/SM)
    tc_gemm<<<dim3(NQKV_/128, M_/64), 256, TC_SMEM>>>(xh, xl, wh, wl, qkv_ptr, NQKV_);
    // 3) RoPE + reorganize -> bf16 split operands
    rope_reorg<<<(B_*H_*64*(T_/4))/256, 256>>>();
    // 4) HMMA causal flash attention (writes g_ah/g_al directly)
    attn_kernel<<<dim3(T_/64, H_, B_), 256, ATT_SMEM>>>();
    // 5) Output projection (HMMA)
    tc_gemm<<<dim3(C_/128, M_/64), 256, TC_SMEM>>>(ah, al, oh, ol, out, C_);
}

// round 14
// speedup vs baseline: 1.2708x; 1.2708x over previous
#include <cuda_runtime.h>
#include <cuda_fp16.h>
#include <math.h>
#include <stdint.h>

#define B_ 2
#define T_ 2048
#define C_ 2048
#define H_ 16
#define D_ 128
#define M_ 4096
#define NQKV_ 6144
#define K_ 2048
#define NCHUNK 32      /* K_/64 */

// ---------------- scratch (device globals: allocation-free) ----------------
__device__ float g_qkv[(size_t)M_*NQKV_];
__device__ __half g_x16[(size_t)M_*C_];                              // A of QKV (single)
__device__ __half g_wh[(size_t)NQKV_*C_], g_wl[(size_t)NQKV_*C_];    // B of QKV (2-split)
__device__ __half g_oh[(size_t)C_*C_],    g_ol[(size_t)C_*C_];       // B of out-proj
__device__ __half g_att[(size_t)M_*C_];                              // attn out (A, single)
__device__ __half g_qh[(size_t)B_*H_*T_*D_];                         // Q (A, single)
__device__ __half g_kh[(size_t)B_*H_*T_*D_], g_kl[(size_t)B_*H_*T_*D_];   // K (B, 2-split)
__device__ __half g_vth[(size_t)B_*H_*D_*T_], g_vtl[(size_t)B_*H_*D_*T_]; // V^T (B, 2-split)

extern __shared__ __align__(16) char dyn_smem[];

// ---------------- sm_80-class primitives (legal on plain sm_103) -----------
__device__ __forceinline__ uint32_t smem_u32(const void* p) {
    uint32_t a;
    asm("{ .reg .u64 t; cvta.to.shared.u64 t, %1; cvt.u32.u64 %0, t; }"
        : "=r"(a) : "l"(p));
    return a;
}
__device__ __forceinline__ void cp16(uint32_t dst, const void* src) {
    asm volatile("cp.async.cg.shared.global [%0], [%1], 16;"
                 :: "r"(dst), "l"(src) : "memory");
}
__device__ __forceinline__ void cp_commit() {
    asm volatile("cp.async.commit_group;" ::: "memory");
}
__device__ __forceinline__ void cp_wait0() {
    asm volatile("cp.async.wait_group 0;" ::: "memory");
}
__device__ __forceinline__ void cp_wait1() {
    asm volatile("cp.async.wait_group 1;" ::: "memory");
}
__device__ __forceinline__ void ldsm_x4(uint32_t* r, uint32_t addr) {
    asm volatile("ldmatrix.sync.aligned.m8n8.x4.shared.b16 {%0,%1,%2,%3}, [%4];"
                 : "=r"(r[0]), "=r"(r[1]), "=r"(r[2]), "=r"(r[3]) : "r"(addr));
}
__device__ __forceinline__ void mma16816(float* c, const uint32_t* a, const uint32_t* b) {
    asm volatile(
        "mma.sync.aligned.m16n8k16.row.col.f32.f16.f16.f32 "
        "{%0,%1,%2,%3}, {%4,%5,%6,%7}, {%8,%9}, {%0,%1,%2,%3};"
        : "+f"(c[0]), "+f"(c[1]), "+f"(c[2]), "+f"(c[3])
        : "r"(a[0]), "r"(a[1]), "r"(a[2]), "r"(a[3]), "r"(b[0]), "r"(b[1]));
}
// SW128 swizzled address inside a [rows][64 fp16] tile (128B rows)
__device__ __forceinline__ uint32_t swz(uint32_t tile_base, int row, int col2 /*bytes*/) {
    return tile_base + ((uint32_t)row << 7) + ((uint32_t)col2 ^ (((uint32_t)row & 7u) << 4));
}
__device__ __forceinline__ uint32_t pack_h2(__half lo, __half hi) {
    return (uint32_t)__half_as_ushort(lo) | ((uint32_t)__half_as_ushort(hi) << 16);
}
__device__ __forceinline__ void hsplit(float f, __half& h, __half& l) {
    h = __float2half_rn(f);
    l = __float2half_rn(f - __half2float(h));
}

// tile loaders: [64 rows][64 fp16] and [128 rows][64 fp16], SW128 swizzled
__device__ __forceinline__ void tile64_async(uint32_t dst, const __half* src,
                                             size_t pitch, int tid)
{
#pragma unroll
    for (int u = 0; u < 2; ++u) {
        const int c = tid*2 + u;
        const int row = c >> 3, seg = (c & 7) * 16;
        uint32_t o = (uint32_t)(row*128 + seg);
        o ^= ((o >> 3) & 0x70);
        cp16(dst + o, (const char*)(src + (size_t)row*pitch) + seg);
    }
}
__device__ __forceinline__ void tile128_async(uint32_t dst, const __half* src,
                                              size_t pitch, int tid)
{
#pragma unroll
    for (int u = 0; u < 4; ++u) {
        const int c = tid*4 + u;
        const int row = c >> 3, seg = (c & 7) * 16;
        uint32_t o = (uint32_t)(row*128 + seg);
        o ^= ((o >> 3) & 0x70);
        cp16(dst + o, (const char*)(src + (size_t)row*pitch) + seg);
    }
}

// ---------------------------------------------------------------------------
// fp32 -> fp16 conversion kernels (single and hi/lo split).
// ---------------------------------------------------------------------------
__global__ void __launch_bounds__(256)
cvt_half(const float* __restrict__ src, __half* __restrict__ dst, int n4)
{
    const int i = blockIdx.x*256 + threadIdx.x;
    if (i >= n4) return;
    const float4 v = ((const float4*)src)[i];
    ((__half2*)dst)[i*2+0] = __floats2half2_rn(v.x, v.y);
    ((__half2*)dst)[i*2+1] = __floats2half2_rn(v.z, v.w);
}
__global__ void __launch_bounds__(256)
split_half(const float* __restrict__ src, __half* __restrict__ hi,
           __half* __restrict__ lo, int n4)
{
    const int i = blockIdx.x*256 + threadIdx.x;
    if (i >= n4) return;
    const float4 v = ((const float4*)src)[i];
    float f[4] = {v.x, v.y, v.z, v.w};
    __half h[4], l[4];
#pragma unroll
    for (int j = 0; j < 4; ++j) hsplit(f[j], h[j], l[j]);
    ((__half2*)hi)[i*2+0] = __halves2half2(h[0], h[1]);
    ((__half2*)hi)[i*2+1] = __halves2half2(h[2], h[3]);
    ((__half2*)lo)[i*2+0] = __halves2half2(l[0], l[1]);
    ((__half2*)lo)[i*2+1] = __halves2half2(l[2], l[3]);
}

// ---------------------------------------------------------------------------
// HMMA fp16 2-term NT GEMM: C = Ah * (Bh + Bl)^T, fp32 accum.
// CTA 128x128, BK=64, 3-stage cp.async, 8 warps (warp tile 64x32).
// ---------------------------------------------------------------------------
#define TCOFF(buf, t) ((uint32_t)(((buf)*3 + (t)) * 16384))   /* t: 0=A,1=Bh,2=Bl */
#define TC_SMEM (9*16384)   /* 144 KB, 3 stages */

__global__ void __launch_bounds__(256, 1)
tc_gemm(const __half* __restrict__ Ah,
        const __half* __restrict__ Bh, const __half* __restrict__ Bl,
        float* __restrict__ Cout, int N)
{
    const uint32_t sbase = smem_u32(dyn_smem);
    const int tid = threadIdx.x, wid = tid >> 5, lane = tid & 31;
    const int wy = wid >> 2, wx = wid & 3;
    const int m0 = blockIdx.y * 128, n0 = blockIdx.x * 128;
    const int r = lane & 7, g = lane >> 3;

    float acc[4][4][4];
#pragma unroll
    for (int i = 0; i < 4; ++i)
#pragma unroll
        for (int j = 0; j < 4; ++j)
#pragma unroll
            for (int e = 0; e < 4; ++e) acc[i][j][e] = 0.0f;

#pragma unroll
    for (int p = 0; p < 2; ++p) {
        tile128_async(sbase + TCOFF(p,0), Ah + (size_t)m0*K_ + p*64, K_, tid);
        tile128_async(sbase + TCOFF(p,1), Bh + (size_t)n0*K_ + p*64, K_, tid);
        tile128_async(sbase + TCOFF(p,2), Bl + (size_t)n0*K_ + p*64, K_, tid);
        cp_commit();
    }

    for (int chunk = 0; chunk < NCHUNK; ++chunk) {
        const int buf = chunk % 3;
        if (chunk == NCHUNK-1) cp_wait0(); else cp_wait1();
        __syncthreads();
        if (chunk + 2 < NCHUNK) {
            const int nb = (chunk + 2) % 3;
            const int k0n = (chunk + 2) * 64;
            tile128_async(sbase + TCOFF(nb,0), Ah + (size_t)m0*K_ + k0n, K_, tid);
            tile128_async(sbase + TCOFF(nb,1), Bh + (size_t)n0*K_ + k0n, K_, tid);
            tile128_async(sbase + TCOFF(nb,2), Bl + (size_t)n0*K_ + k0n, K_, tid);
            cp_commit();
        }
        const uint32_t aT = sbase + TCOFF(buf,0);
        const uint32_t bH = sbase + TCOFF(buf,1), bL = sbase + TCOFF(buf,2);
#pragma unroll
        for (int ks = 0; ks < 4; ++ks) {
            uint32_t ah[4][4], bh[4][2], blr[4][2];
            const int colA = ks*32 + (g>>1)*16;
            const int colB = ks*32 + (g&1)*16;
#pragma unroll
            for (int i = 0; i < 4; ++i) {
                const int row = wy*64 + i*16 + r + (g&1)*8;
                ldsm_x4(ah[i], swz(aT, row, colA));
            }
#pragma unroll
            for (int jj = 0; jj < 2; ++jj) {
                const int row = wx*32 + jj*16 + r + (g>>1)*8;
                uint32_t t[4];
                ldsm_x4(t, swz(bH, row, colB));
                bh[jj*2][0]=t[0]; bh[jj*2][1]=t[1];
                bh[jj*2+1][0]=t[2]; bh[jj*2+1][1]=t[3];
                ldsm_x4(t, swz(bL, row, colB));
                blr[jj*2][0]=t[0]; blr[jj*2][1]=t[1];
                blr[jj*2+1][0]=t[2]; blr[jj*2+1][1]=t[3];
            }
#pragma unroll
            for (int i = 0; i < 4; ++i)
#pragma unroll
                for (int j = 0; j < 4; ++j)
                    mma16816(acc[i][j], ah[i], bh[j]);
#pragma unroll
            for (int i = 0; i < 4; ++i)
#pragma unroll
                for (int j = 0; j < 4; ++j)
                    mma16816(acc[i][j], ah[i], blr[j]);
        }
    }
#pragma unroll
    for (int i = 0; i < 4; ++i) {
        const int rm = m0 + wy*64 + i*16 + (lane >> 2);
#pragma unroll
        for (int j = 0; j < 4; ++j) {
            const int cn = n0 + wx*32 + j*8 + (lane & 3)*2;
            *(float2*)&Cout[(size_t)rm*N + cn]     = make_float2(acc[i][j][0], acc[i][j][1]);
            *(float2*)&Cout[(size_t)(rm+8)*N + cn] = make_float2(acc[i][j][2], acc[i][j][3]);
        }
    }
}

// ---------------------------------------------------------------------------
// RoPE + reorganize -> fp16: qh [B,H,T,D]; kh/kl [B,H,T,D]; vth/vtl [B,H,D,T].
// ---------------------------------------------------------------------------
__global__ void rope_reorg()
{
    const int idx = blockIdx.x * 256 + threadIdx.x;
    const int t4 = idx & 511;
    const int i  = (idx >> 9) & 63;
    const int h  = (idx >> 15) & (H_ - 1);
    const int b  = idx >> 19;
    const int bh = b*H_ + h;
    const int col = h*D_ + i;

    const float mlt = (float)(-9.210340371976184 / 128.0);
    const float div = expf((float)(2*i) * mlt);

#pragma unroll
    for (int u = 0; u < 4; ++u) {
        const int t = t4*4 + u;
        const size_t row = (size_t)(b*T_ + t) * NQKV_;
        const float q1 = g_qkv[row + 0*C_ + col];
        const float q2 = g_qkv[row + 0*C_ + col + 64];
        const float k1 = g_qkv[row + 1*C_ + col];
        const float k2 = g_qkv[row + 1*C_ + col + 64];
        const float v1 = g_qkv[row + 2*C_ + col];
        const float v2 = g_qkv[row + 2*C_ + col + 64];

        float s, c;
        sincosf((float)t * div, &s, &c);
        const float qa = q1*c - q2*s, qb2 = q2*c + q1*s;
        const float ka = k1*c - k2*s, kb2 = k2*c + k1*s;

        const size_t off = ((size_t)bh * T_ + t) * D_ + i;
        g_qh[off]      = __float2half_rn(qa);
        g_qh[off + 64] = __float2half_rn(qb2);
        __half hh, ll;
        hsplit(ka,  hh, ll); g_kh[off]      = hh; g_kl[off]      = ll;
        hsplit(kb2, hh, ll); g_kh[off + 64] = hh; g_kl[off + 64] = ll;
        const size_t koff = ((size_t)bh * D_ + i) * T_ + t;
        hsplit(v1, hh, ll); g_vth[koff]         = hh; g_vtl[koff]         = ll;
        hsplit(v2, hh, ll); g_vth[koff + 64*T_] = hh; g_vtl[koff + 64*T_] = ll;
    }
}

// ---------------------------------------------------------------------------
// HMMA causal flash attention, fp16 2-term (Q,P single; K,V 2-split), fp32
// softmax. Epilogue writes fp16 attn-out in the reference layout.
// smem: qh 16K | KV[2]: kh 16K, kl 16K, vth 16K, vtl 16K | Ss 17408 |
//       Ph 8192 | m/l/sc 768  -> 173824 B
// ---------------------------------------------------------------------------
#define AQ_OFF   0u
#define AKV_OFF(buf) (16384u + (buf)*65536u)
#define ASS_OFF  147456u
#define APH_OFF  164864u
#define AML_OFF  173056u
#define ATT_SMEM 173824

__global__ void __launch_bounds__(256, 1)
attn_kernel()
{
    const uint32_t sb = smem_u32(dyn_smem);
    float* Ss  = (float*)(dyn_smem + ASS_OFF);
    float* m_s = (float*)(dyn_smem + AML_OFF);
    float* l_s = m_s + 64;
    float* sc_s = l_s + 64;

    const int tid = threadIdx.x, wid = tid >> 5, lane = tid & 31;
    const int r = lane & 7, g = lane >> 3;
    const int wq = wid >> 1, wk = wid & 1;
    const int qt = (gridDim.x - 1) - blockIdx.x;
    const int h = blockIdx.y, b = blockIdx.z;
    const size_t hoff  = (size_t)(b*H_ + h) * T_ * D_;
    const size_t hofft = (size_t)(b*H_ + h) * D_ * T_;
    const int q0 = qt * 64;

    tile64_async(sb + AQ_OFF + 0,    g_qh + hoff + (size_t)q0*D_,      D_, tid);
    tile64_async(sb + AQ_OFF + 8192, g_qh + hoff + (size_t)q0*D_ + 64, D_, tid);
    {
        const uint32_t kv = sb + AKV_OFF(0);
        tile64_async (kv + 0,     g_kh + hoff, D_, tid);
        tile64_async (kv + 8192,  g_kh + hoff + 64, D_, tid);
        tile64_async (kv + 16384, g_kl + hoff, D_, tid);
        tile64_async (kv + 24576, g_kl + hoff + 64, D_, tid);
        tile128_async(kv + 32768, g_vth + hofft, T_, tid);
        tile128_async(kv + 49152, g_vtl + hofft, T_, tid);
    }
    cp_commit(); cp_wait0();
    if (tid < 64) { m_s[tid] = -INFINITY; l_s[tid] = 0.0f; }
    __syncthreads();

    float acc[8][4];
#pragma unroll
    for (int j = 0; j < 8; ++j)
#pragma unroll
        for (int e = 0; e < 4; ++e) acc[j][e] = 0.0f;

    const float scl = 0.08838834764831845f;
    const int sr = tid >> 2, sq = tid & 3;

    for (int kt = 0; kt <= qt; ++kt) {
        const int buf = kt & 1;
        if (kt < qt) {
            const int k0n = (kt + 1) * 64;
            const uint32_t kv = sb + AKV_OFF(buf^1);
            tile64_async (kv + 0,     g_kh + hoff + (size_t)k0n*D_, D_, tid);
            tile64_async (kv + 8192,  g_kh + hoff + (size_t)k0n*D_ + 64, D_, tid);
            tile64_async (kv + 16384, g_kl + hoff + (size_t)k0n*D_, D_, tid);
            tile64_async (kv + 24576, g_kl + hoff + (size_t)k0n*D_ + 64, D_, tid);
            tile128_async(kv + 32768, g_vth + hofft + k0n, T_, tid);
            tile128_async(kv + 49152, g_vtl + hofft + k0n, T_, tid);
            cp_commit();
        }
        const uint32_t sQH = sb + AQ_OFF;
        const uint32_t sKH = sb + AKV_OFF(buf), sKL = sKH + 16384;
        const uint32_t sVH = sb + AKV_OFF(buf) + 32768, sVL = sVH + 16384;

        // ---- S = Q K^T (2-term) ----
        {
            float s[4][4];
#pragma unroll
            for (int j = 0; j < 4; ++j)
#pragma unroll
                for (int e = 0; e < 4; ++e) s[j][e] = 0.0f;
#pragma unroll
            for (int ks = 0; ks < 8; ++ks) {
                const uint32_t subo = (uint32_t)(ks >> 2) * 8192u;
                const int colA = (ks & 3)*32 + (g>>1)*16;
                const int colB = (ks & 3)*32 + (g&1)*16;
                uint32_t ah[4], bh[4][2], bl[4][2];
                const int rowA = wq*16 + r + (g&1)*8;
                ldsm_x4(ah, swz(sQH + subo, rowA, colA));
#pragma unroll
                for (int jj = 0; jj < 2; ++jj) {
                    const int rowB = wk*32 + jj*16 + r + (g>>1)*8;
                    uint32_t t[4];
                    ldsm_x4(t, swz(sKH + subo, rowB, colB));
                    bh[jj*2][0]=t[0]; bh[jj*2][1]=t[1];
                    bh[jj*2+1][0]=t[2]; bh[jj*2+1][1]=t[3];
                    ldsm_x4(t, swz(sKL + subo, rowB, colB));
                    bl[jj*2][0]=t[0]; bl[jj*2][1]=t[1];
                    bl[jj*2+1][0]=t[2]; bl[jj*2+1][1]=t[3];
                }
#pragma unroll
                for (int j = 0; j < 4; ++j) mma16816(s[j], ah, bh[j]);
#pragma unroll
                for (int j = 0; j < 4; ++j) mma16816(s[j], ah, bl[j]);
            }
#pragma unroll
            for (int j = 0; j < 4; ++j) {
                const int row0 = wq*16 + (lane >> 2);
                const int cc = wk*32 + j*8 + (lane & 3)*2;
                *(float2*)&Ss[row0*68 + cc]     = make_float2(s[j][0]*scl, s[j][1]*scl);
                *(float2*)&Ss[(row0+8)*68 + cc] = make_float2(s[j][2]*scl, s[j][3]*scl);
            }
        }
        __syncthreads();
        // ---- softmax (fp32) + write P (fp16 single) ----
        {
            const int k0 = kt * 64;
            float* row = Ss + sr*68;
            int kmax = q0 + sr - k0 + 1;
            if (kmax > 64) kmax = 64;
            const float m_old = m_s[sr];
            float mx = m_old;
#pragma unroll
            for (int c0 = 0; c0 < 16; ++c0) {
                const int c = sq*16 + c0;
                if (c < kmax) mx = fmaxf(mx, row[c]);
            }
            mx = fmaxf(mx, __shfl_xor_sync(0xffffffff, mx, 1));
            mx = fmaxf(mx, __shfl_xor_sync(0xffffffff, mx, 2));
            float sum = 0.0f;
#pragma unroll
            for (int cp = 0; cp < 8; ++cp) {
                const int c = sq*16 + cp*2;
                const float p0 = (c   < kmax) ? __expf(row[c]   - mx) : 0.0f;
                const float p1 = (c+1 < kmax) ? __expf(row[c+1] - mx) : 0.0f;
                sum += p0 + p1;
                *(uint32_t*)(dyn_smem + swz(APH_OFF, sr, c*2)) =
                    pack_h2(__float2half_rn(p0), __float2half_rn(p1));
            }
            sum += __shfl_xor_sync(0xffffffff, sum, 1);
            sum += __shfl_xor_sync(0xffffffff, sum, 2);
            if (sq == 0) {
                const float sc = __expf(m_old - mx);
                m_s[sr]  = mx;
                l_s[sr]  = l_s[sr] * sc + sum;
                sc_s[sr] = sc;
            }
        }
        __syncthreads();
        // ---- O = O*sc + P V (2-term) ----
        {
            const int row0 = wq*16 + (lane >> 2);
            const float sc0 = sc_s[row0], sc1 = sc_s[row0 + 8];
#pragma unroll
            for (int j = 0; j < 8; ++j) {
                acc[j][0] *= sc0; acc[j][1] *= sc0;
                acc[j][2] *= sc1; acc[j][3] *= sc1;
            }
#pragma unroll
            for (int ks = 0; ks < 4; ++ks) {
                const int colA = ks*32 + (g>>1)*16;
                const int colB = ks*32 + (g&1)*16;
                uint32_t pah[4], bh[8][2], bl[8][2];
                const int rowA = wq*16 + r + (g&1)*8;
                ldsm_x4(pah, swz(sb + APH_OFF, rowA, colA));
#pragma unroll
                for (int jj = 0; jj < 4; ++jj) {
                    const int rowB = wk*64 + jj*16 + r + (g>>1)*8;
                    uint32_t t[4];
                    ldsm_x4(t, swz(sVH, rowB, colB));
                    bh[jj*2][0]=t[0]; bh[jj*2][1]=t[1];
                    bh[jj*2+1][0]=t[2]; bh[jj*2+1][1]=t[3];
                    ldsm_x4(t, swz(sVL, rowB, colB));
                    bl[jj*2][0]=t[0]; bl[jj*2][1]=t[1];
                    bl[jj*2+1][0]=t[2]; bl[jj*2+1][1]=t[3];
                }
#pragma unroll
                for (int j = 0; j < 8; ++j) mma16816(acc[j], pah, bh[j]);
#pragma unroll
                for (int j = 0; j < 8; ++j) mma16816(acc[j], pah, bl[j]);
            }
        }
        if (kt < qt) cp_wait0();
        __syncthreads();
    }

    // epilogue: normalize + fp16, reference layout
    {
        const int row0 = wq*16 + (lane >> 2);
        const float inv0 = 1.0f / l_s[row0];
        const float inv1 = 1.0f / l_s[row0 + 8];
        const int t0 = q0 + row0, t1 = t0 + 8;
        const int rowA = 128*h + (t0 >> 4), rowB2 = 128*h + (t1 >> 4);
        const int cbase0 = ((t0 & 15) << 7), cbase1 = ((t1 & 15) << 7);
#pragma unroll
        for (int j = 0; j < 8; ++j) {
            const int d = wk*64 + j*8 + (lane & 3)*2;
            const size_t i0 = (size_t)(b*T_ + rowA)*C_ + cbase0 + d;
            const size_t i1 = (size_t)(b*T_ + rowB2)*C_ + cbase1 + d;
            *(uint32_t*)&g_att[i0] = pack_h2(__float2half_rn(acc[j][0]*inv0),
                                             __float2half_rn(acc[j][1]*inv0));
            *(uint32_t*)&g_att[i1] = pack_h2(__float2half_rn(acc[j][2]*inv1),
                                             __float2half_rn(acc[j][3]*inv1));
        }
    }
}

// ---------------------------------------------------------------------------
extern "C" void kernel_launch(void* const* d_in, const int* in_sizes, int n_in,
                              void* d_out, int out_size)
{
    const float* x = nullptr; const float* qkv_w = nullptr; const float* out_w = nullptr;
    for (int i = 0; i < n_in; ++i) {
        if      (in_sizes[i] == B_*T_*C_) x     = (const float*)d_in[i];
        else if (in_sizes[i] == 3*C_*C_)  qkv_w = (const float*)d_in[i];
        else if (in_sizes[i] == C_*C_)    out_w = (const float*)d_in[i];
    }
    if (!x)     x     = (const float*)d_in[0];
    if (!qkv_w) qkv_w = (const float*)d_in[1];
    if (!out_w) out_w = (const float*)d_in[2];
    float* out = (float*)d_out;

    float *qkv_ptr;
    __half *x16, *wh, *wl, *oh, *ol, *att;
    cudaGetSymbolAddress((void**)&qkv_ptr, g_qkv);
    cudaGetSymbolAddress((void**)&x16, g_x16);
    cudaGetSymbolAddress((void**)&wh, g_wh); cudaGetSymbolAddress((void**)&wl, g_wl);
    cudaGetSymbolAddress((void**)&oh, g_oh); cudaGetSymbolAddress((void**)&ol, g_ol);
    cudaGetSymbolAddress((void**)&att, g_att);

    cudaFuncSetAttribute(tc_gemm, cudaFuncAttributeMaxDynamicSharedMemorySize, TC_SMEM);
    cudaFuncSetAttribute(attn_kernel, cudaFuncAttributeMaxDynamicSharedMemorySize, ATT_SMEM);

    // 1) fp32 -> fp16 conversions (A single, B split)
    cvt_half<<<(M_*C_/4 + 255)/256, 256>>>(x, x16, M_*C_/4);
    split_half<<<(NQKV_*C_/4 + 255)/256, 256>>>(qkv_w, wh, wl, NQKV_*C_/4);
    split_half<<<(C_*C_/4 + 255)/256, 256>>>(out_w, oh, ol, C_*C_/4);
    // 2) QKV projection (HMMA, 2-term)
    tc_gemm<<<dim3(NQKV_/128, M_/128), 256, TC_SMEM>>>(x16, wh, wl, qkv_ptr, NQKV_);
    // 3) RoPE + reorganize -> fp16 operands
    rope_reorg<<<(B_*H_*64*(T_/4))/256, 256>>>();
    // 4) HMMA causal flash attention (writes g_att directly)
    attn_kernel<<<dim3(T_/64, H_, B_), 256, ATT_SMEM>>>();
    // 5) Output projection (HMMA, 2-term)
    tc_gemm<<<dim3(C_/128, M_/128), 256, TC_SMEM>>>(att, oh, ol, out, C_);
}

// round 15
// speedup vs baseline: 1.6107x; 1.2674x over previous
#include <cuda_runtime.h>
#include <cuda_fp16.h>
#include <math.h>
#include <stdint.h>

#define B_ 2
#define T_ 2048
#define C_ 2048
#define H_ 16
#define D_ 128
#define M_ 4096
#define NQKV_ 6144
#define K_ 2048
#define NCHUNK 32      /* K_/64 */

// ---------------- scratch (device globals: allocation-free) ----------------
__device__ float g_qkv[(size_t)M_*NQKV_];
__device__ __half g_x16[(size_t)M_*C_];                              // A of QKV
__device__ __half g_w16[(size_t)NQKV_*C_];                           // B of QKV (single)
__device__ __half g_o16[(size_t)C_*C_];                              // B of out-proj (single)
__device__ __half g_att[(size_t)M_*C_];                              // attn out (A of out-proj)
__device__ __half g_qh[(size_t)B_*H_*T_*D_];                         // Q (single)
__device__ __half g_kh[(size_t)B_*H_*T_*D_], g_kl[(size_t)B_*H_*T_*D_];   // K (2-split)
__device__ __half g_vth[(size_t)B_*H_*D_*T_], g_vtl[(size_t)B_*H_*D_*T_]; // V^T (2-split)

extern __shared__ __align__(16) char dyn_smem[];

// ---------------- sm_80-class primitives (legal on plain sm_103) -----------
__device__ __forceinline__ uint32_t smem_u32(const void* p) {
    uint32_t a;
    asm("{ .reg .u64 t; cvta.to.shared.u64 t, %1; cvt.u32.u64 %0, t; }"
        : "=r"(a) : "l"(p));
    return a;
}
__device__ __forceinline__ void cp16(uint32_t dst, const void* src) {
    asm volatile("cp.async.cg.shared.global [%0], [%1], 16;"
                 :: "r"(dst), "l"(src) : "memory");
}
__device__ __forceinline__ void cp_commit() {
    asm volatile("cp.async.commit_group;" ::: "memory");
}
__device__ __forceinline__ void cp_wait0() {
    asm volatile("cp.async.wait_group 0;" ::: "memory");
}
__device__ __forceinline__ void cp_wait1() {
    asm volatile("cp.async.wait_group 1;" ::: "memory");
}
__device__ __forceinline__ void ldsm_x4(uint32_t* r, uint32_t addr) {
    asm volatile("ldmatrix.sync.aligned.m8n8.x4.shared.b16 {%0,%1,%2,%3}, [%4];"
                 : "=r"(r[0]), "=r"(r[1]), "=r"(r[2]), "=r"(r[3]) : "r"(addr));
}
__device__ __forceinline__ void mma16816(float* c, const uint32_t* a, const uint32_t* b) {
    asm volatile(
        "mma.sync.aligned.m16n8k16.row.col.f32.f16.f16.f32 "
        "{%0,%1,%2,%3}, {%4,%5,%6,%7}, {%8,%9}, {%0,%1,%2,%3};"
        : "+f"(c[0]), "+f"(c[1]), "+f"(c[2]), "+f"(c[3])
        : "r"(a[0]), "r"(a[1]), "r"(a[2]), "r"(a[3]), "r"(b[0]), "r"(b[1]));
}
// SW128 swizzled address inside a [rows][64 fp16] tile (128B rows)
__device__ __forceinline__ uint32_t swz(uint32_t tile_base, int row, int col2 /*bytes*/) {
    return tile_base + ((uint32_t)row << 7) + ((uint32_t)col2 ^ (((uint32_t)row & 7u) << 4));
}
__device__ __forceinline__ uint32_t pack_h2(__half lo, __half hi) {
    return (uint32_t)__half_as_ushort(lo) | ((uint32_t)__half_as_ushort(hi) << 16);
}
__device__ __forceinline__ void hsplit(float f, __half& h, __half& l) {
    h = __float2half_rn(f);
    l = __float2half_rn(f - __half2float(h));
}

// tile loaders: [64 rows][64 fp16] and [128 rows][64 fp16], SW128 swizzled
__device__ __forceinline__ void tile64_async(uint32_t dst, const __half* src,
                                             size_t pitch, int tid)
{
#pragma unroll
    for (int u = 0; u < 2; ++u) {
        const int c = tid*2 + u;
        const int row = c >> 3, seg = (c & 7) * 16;
        uint32_t o = (uint32_t)(row*128 + seg);
        o ^= ((o >> 3) & 0x70);
        cp16(dst + o, (const char*)(src + (size_t)row*pitch) + seg);
    }
}
__device__ __forceinline__ void tile128_async(uint32_t dst, const __half* src,
                                              size_t pitch, int tid)
{
#pragma unroll
    for (int u = 0; u < 4; ++u) {
        const int c = tid*4 + u;
        const int row = c >> 3, seg = (c & 7) * 16;
        uint32_t o = (uint32_t)(row*128 + seg);
        o ^= ((o >> 3) & 0x70);
        cp16(dst + o, (const char*)(src + (size_t)row*pitch) + seg);
    }
}

// ---------------------------------------------------------------------------
// fp32 -> fp16 conversion kernels (single and hi/lo split).
// ---------------------------------------------------------------------------
__global__ void __launch_bounds__(256)
cvt_half(const float* __restrict__ src, __half* __restrict__ dst, int n4)
{
    const int i = blockIdx.x*256 + threadIdx.x;
    if (i >= n4) return;
    const float4 v = ((const float4*)src)[i];
    ((__half2*)dst)[i*2+0] = __floats2half2_rn(v.x, v.y);
    ((__half2*)dst)[i*2+1] = __floats2half2_rn(v.z, v.w);
}

// ---------------------------------------------------------------------------
// HMMA fp16 NT GEMM: C = A * B^T, fp32 accum. CTA 128x128, BK=64,
// 3-stage cp.async, 8 warps (warp tile 64x32).
// ---------------------------------------------------------------------------
#define TCOFF(buf, t) ((uint32_t)(((buf)*2 + (t)) * 16384))   /* t: 0=A,1=B */
#define TC_SMEM (6*16384)   /* 96 KB, 3 stages */

__global__ void __launch_bounds__(256, 1)
tc_gemm(const __half* __restrict__ Ah, const __half* __restrict__ Bh,
        float* __restrict__ Cout, int N)
{
    const uint32_t sbase = smem_u32(dyn_smem);
    const int tid = threadIdx.x, wid = tid >> 5, lane = tid & 31;
    const int wy = wid >> 2, wx = wid & 3;
    const int m0 = blockIdx.y * 128, n0 = blockIdx.x * 128;
    const int r = lane & 7, g = lane >> 3;

    float acc[4][4][4];
#pragma unroll
    for (int i = 0; i < 4; ++i)
#pragma unroll
        for (int j = 0; j < 4; ++j)
#pragma unroll
            for (int e = 0; e < 4; ++e) acc[i][j][e] = 0.0f;

#pragma unroll
    for (int p = 0; p < 2; ++p) {
        tile128_async(sbase + TCOFF(p,0), Ah + (size_t)m0*K_ + p*64, K_, tid);
        tile128_async(sbase + TCOFF(p,1), Bh + (size_t)n0*K_ + p*64, K_, tid);
        cp_commit();
    }

    for (int chunk = 0; chunk < NCHUNK; ++chunk) {
        const int buf = chunk % 3;
        if (chunk == NCHUNK-1) cp_wait0(); else cp_wait1();
        __syncthreads();
        if (chunk + 2 < NCHUNK) {
            const int nb = (chunk + 2) % 3;
            const int k0n = (chunk + 2) * 64;
            tile128_async(sbase + TCOFF(nb,0), Ah + (size_t)m0*K_ + k0n, K_, tid);
            tile128_async(sbase + TCOFF(nb,1), Bh + (size_t)n0*K_ + k0n, K_, tid);
            cp_commit();
        }
        const uint32_t aT = sbase + TCOFF(buf,0);
        const uint32_t bT = sbase + TCOFF(buf,1);
#pragma unroll
        for (int ks = 0; ks < 4; ++ks) {
            uint32_t ah[4][4], bh[4][2];
            const int colA = ks*32 + (g>>1)*16;
            const int colB = ks*32 + (g&1)*16;
#pragma unroll
            for (int i = 0; i < 4; ++i) {
                const int row = wy*64 + i*16 + r + (g&1)*8;
                ldsm_x4(ah[i], swz(aT, row, colA));
            }
#pragma unroll
            for (int jj = 0; jj < 2; ++jj) {
                const int row = wx*32 + jj*16 + r + (g>>1)*8;
                uint32_t t[4];
                ldsm_x4(t, swz(bT, row, colB));
                bh[jj*2][0]=t[0]; bh[jj*2][1]=t[1];
                bh[jj*2+1][0]=t[2]; bh[jj*2+1][1]=t[3];
            }
#pragma unroll
            for (int i = 0; i < 4; ++i)
#pragma unroll
                for (int j = 0; j < 4; ++j)
                    mma16816(acc[i][j], ah[i], bh[j]);
        }
    }
#pragma unroll
    for (int i = 0; i < 4; ++i) {
        const int rm = m0 + wy*64 + i*16 + (lane >> 2);
#pragma unroll
        for (int j = 0; j < 4; ++j) {
            const int cn = n0 + wx*32 + j*8 + (lane & 3)*2;
            *(float2*)&Cout[(size_t)rm*N + cn]     = make_float2(acc[i][j][0], acc[i][j][1]);
            *(float2*)&Cout[(size_t)(rm+8)*N + cn] = make_float2(acc[i][j][2], acc[i][j][3]);
        }
    }
}

// ---------------------------------------------------------------------------
// RoPE + reorganize -> fp16: qh [B,H,T,D]; kh/kl [B,H,T,D]; vth/vtl [B,H,D,T].
// ---------------------------------------------------------------------------
__global__ void rope_reorg()
{
    const int idx = blockIdx.x * 256 + threadIdx.x;
    const int t4 = idx & 511;
    const int i  = (idx >> 9) & 63;
    const int h  = (idx >> 15) & (H_ - 1);
    const int b  = idx >> 19;
    const int bh = b*H_ + h;
    const int col = h*D_ + i;

    const float mlt = (float)(-9.210340371976184 / 128.0);
    const float div = expf((float)(2*i) * mlt);

#pragma unroll
    for (int u = 0; u < 4; ++u) {
        const int t = t4*4 + u;
        const size_t row = (size_t)(b*T_ + t) * NQKV_;
        const float q1 = g_qkv[row + 0*C_ + col];
        const float q2 = g_qkv[row + 0*C_ + col + 64];
        const float k1 = g_qkv[row + 1*C_ + col];
        const float k2 = g_qkv[row + 1*C_ + col + 64];
        const float v1 = g_qkv[row + 2*C_ + col];
        const float v2 = g_qkv[row + 2*C_ + col + 64];

        float s, c;
        sincosf((float)t * div, &s, &c);
        const float qa = q1*c - q2*s, qb2 = q2*c + q1*s;
        const float ka = k1*c - k2*s, kb2 = k2*c + k1*s;

        const size_t off = ((size_t)bh * T_ + t) * D_ + i;
        g_qh[off]      = __float2half_rn(qa);
        g_qh[off + 64] = __float2half_rn(qb2);
        __half hh, ll;
        hsplit(ka,  hh, ll); g_kh[off]      = hh; g_kl[off]      = ll;
        hsplit(kb2, hh, ll); g_kh[off + 64] = hh; g_kl[off + 64] = ll;
        const size_t koff = ((size_t)bh * D_ + i) * T_ + t;
        hsplit(v1, hh, ll); g_vth[koff]         = hh; g_vtl[koff]         = ll;
        hsplit(v2, hh, ll); g_vth[koff + 64*T_] = hh; g_vtl[koff + 64*T_] = ll;
    }
}

// ---------------------------------------------------------------------------
// HMMA causal flash attention (unchanged from R14, passed): Q,P single fp16;
// K,V 2-split; fp32 softmax. Epilogue writes fp16 attn-out, reference layout.
// ---------------------------------------------------------------------------
#define AQ_OFF   0u
#define AKV_OFF(buf) (16384u + (buf)*65536u)
#define ASS_OFF  147456u
#define APH_OFF  164864u
#define AML_OFF  173056u
#define ATT_SMEM 173824

__global__ void __launch_bounds__(256, 1)
attn_kernel()
{
    const uint32_t sb = smem_u32(dyn_smem);
    float* Ss  = (float*)(dyn_smem + ASS_OFF);
    float* m_s = (float*)(dyn_smem + AML_OFF);
    float* l_s = m_s + 64;
    float* sc_s = l_s + 64;

    const int tid = threadIdx.x, wid = tid >> 5, lane = tid & 31;
    const int r = lane & 7, g = lane >> 3;
    const int wq = wid >> 1, wk = wid & 1;
    const int qt = (gridDim.x - 1) - blockIdx.x;
    const int h = blockIdx.y, b = blockIdx.z;
    const size_t hoff  = (size_t)(b*H_ + h) * T_ * D_;
    const size_t hofft = (size_t)(b*H_ + h) * D_ * T_;
    const int q0 = qt * 64;

    tile64_async(sb + AQ_OFF + 0,    g_qh + hoff + (size_t)q0*D_,      D_, tid);
    tile64_async(sb + AQ_OFF + 8192, g_qh + hoff + (size_t)q0*D_ + 64, D_, tid);
    {
        const uint32_t kv = sb + AKV_OFF(0);
        tile64_async (kv + 0,     g_kh + hoff, D_, tid);
        tile64_async (kv + 8192,  g_kh + hoff + 64, D_, tid);
        tile64_async (kv + 16384, g_kl + hoff, D_, tid);
        tile64_async (kv + 24576, g_kl + hoff + 64, D_, tid);
        tile128_async(kv + 32768, g_vth + hofft, T_, tid);
        tile128_async(kv + 49152, g_vtl + hofft, T_, tid);
    }
    cp_commit(); cp_wait0();
    if (tid < 64) { m_s[tid] = -INFINITY; l_s[tid] = 0.0f; }
    __syncthreads();

    float acc[8][4];
#pragma unroll
    for (int j = 0; j < 8; ++j)
#pragma unroll
        for (int e = 0; e < 4; ++e) acc[j][e] = 0.0f;

    const float scl = 0.08838834764831845f;
    const int sr = tid >> 2, sq = tid & 3;

    for (int kt = 0; kt <= qt; ++kt) {
        const int buf = kt & 1;
        if (kt < qt) {
            const int k0n = (kt + 1) * 64;
            const uint32_t kv = sb + AKV_OFF(buf^1);
            tile64_async (kv + 0,     g_kh + hoff + (size_t)k0n*D_, D_, tid);
            tile64_async (kv + 8192,  g_kh + hoff + (size_t)k0n*D_ + 64, D_, tid);
            tile64_async (kv + 16384, g_kl + hoff + (size_t)k0n*D_, D_, tid);
            tile64_async (kv + 24576, g_kl + hoff + (size_t)k0n*D_ + 64, D_, tid);
            tile128_async(kv + 32768, g_vth + hofft + k0n, T_, tid);
            tile128_async(kv + 49152, g_vtl + hofft + k0n, T_, tid);
            cp_commit();
        }
        const uint32_t sQH = sb + AQ_OFF;
        const uint32_t sKH = sb + AKV_OFF(buf), sKL = sKH + 16384;
        const uint32_t sVH = sb + AKV_OFF(buf) + 32768, sVL = sVH + 16384;

        // ---- S = Q K^T (2-term) ----
        {
            float s[4][4];
#pragma unroll
            for (int j = 0; j < 4; ++j)
#pragma unroll
                for (int e = 0; e < 4; ++e) s[j][e] = 0.0f;
#pragma unroll
            for (int ks = 0; ks < 8; ++ks) {
                const uint32_t subo = (uint32_t)(ks >> 2) * 8192u;
                const int colA = (ks & 3)*32 + (g>>1)*16;
                const int colB = (ks & 3)*32 + (g&1)*16;
                uint32_t ah[4], bh[4][2], bl[4][2];
                const int rowA = wq*16 + r + (g&1)*8;
                ldsm_x4(ah, swz(sQH + subo, rowA, colA));
#pragma unroll
                for (int jj = 0; jj < 2; ++jj) {
                    const int rowB = wk*32 + jj*16 + r + (g>>1)*8;
                    uint32_t t[4];
                    ldsm_x4(t, swz(sKH + subo, rowB, colB));
                    bh[jj*2][0]=t[0]; bh[jj*2][1]=t[1];
                    bh[jj*2+1][0]=t[2]; bh[jj*2+1][1]=t[3];
                    ldsm_x4(t, swz(sKL + subo, rowB, colB));
                    bl[jj*2][0]=t[0]; bl[jj*2][1]=t[1];
                    bl[jj*2+1][0]=t[2]; bl[jj*2+1][1]=t[3];
                }
#pragma unroll
                for (int j = 0; j < 4; ++j) mma16816(s[j], ah, bh[j]);
#pragma unroll
                for (int j = 0; j < 4; ++j) mma16816(s[j], ah, bl[j]);
            }
#pragma unroll
            for (int j = 0; j < 4; ++j) {
                const int row0 = wq*16 + (lane >> 2);
                const int cc = wk*32 + j*8 + (lane & 3)*2;
                *(float2*)&Ss[row0*68 + cc]     = make_float2(s[j][0]*scl, s[j][1]*scl);
                *(float2*)&Ss[(row0+8)*68 + cc] = make_float2(s[j][2]*scl, s[j][3]*scl);
            }
        }
        __syncthreads();
        // ---- softmax (fp32) + write P (fp16 single) ----
        {
            const int k0 = kt * 64;
            float* row = Ss + sr*68;
            int kmax = q0 + sr - k0 + 1;
            if (kmax > 64) kmax = 64;
            const float m_old = m_s[sr];
            float mx = m_old;
#pragma unroll
            for (int c0 = 0; c0 < 16; ++c0) {
                const int c = sq*16 + c0;
                if (c < kmax) mx = fmaxf(mx, row[c]);
            }
            mx = fmaxf(mx, __shfl_xor_sync(0xffffffff, mx, 1));
            mx = fmaxf(mx, __shfl_xor_sync(0xffffffff, mx, 2));
            float sum = 0.0f;
#pragma unroll
            for (int cp = 0; cp < 8; ++cp) {
                const int c = sq*16 + cp*2;
                const float p0 = (c   < kmax) ? __expf(row[c]   - mx) : 0.0f;
                const float p1 = (c+1 < kmax) ? __expf(row[c+1] - mx) : 0.0f;
                sum += p0 + p1;
                *(uint32_t*)(dyn_smem + swz(APH_OFF, sr, c*2)) =
                    pack_h2(__float2half_rn(p0), __float2half_rn(p1));
            }
            sum += __shfl_xor_sync(0xffffffff, sum, 1);
            sum += __shfl_xor_sync(0xffffffff, sum, 2);
            if (sq == 0) {
                const float sc = __expf(m_old - mx);
                m_s[sr]  = mx;
                l_s[sr]  = l_s[sr] * sc + sum;
                sc_s[sr] = sc;
            }
        }
        __syncthreads();
        // ---- O = O*sc + P V (2-term) ----
        {
            const int row0 = wq*16 + (lane >> 2);
            const float sc0 = sc_s[row0], sc1 = sc_s[row0 + 8];
#pragma unroll
            for (int j = 0; j < 8; ++j) {
                acc[j][0] *= sc0; acc[j][1] *= sc0;
                acc[j][2] *= sc1; acc[j][3] *= sc1;
            }
#pragma unroll
            for (int ks = 0; ks < 4; ++ks) {
                const int colA = ks*32 + (g>>1)*16;
                const int colB = ks*32 + (g&1)*16;
                uint32_t pah[4], bh[8][2], bl[8][2];
                const int rowA = wq*16 + r + (g&1)*8;
                ldsm_x4(pah, swz(sb + APH_OFF, rowA, colA));
#pragma unroll
                for (int jj = 0; jj < 4; ++jj) {
                    const int rowB = wk*64 + jj*16 + r + (g>>1)*8;
                    uint32_t t[4];
                    ldsm_x4(t, swz(sVH, rowB, colB));
                    bh[jj*2][0]=t[0]; bh[jj*2][1]=t[1];
                    bh[jj*2+1][0]=t[2]; bh[jj*2+1][1]=t[3];
                    ldsm_x4(t, swz(sVL, rowB, colB));
                    bl[jj*2][0]=t[0]; bl[jj*2][1]=t[1];
                    bl[jj*2+1][0]=t[2]; bl[jj*2+1][1]=t[3];
                }
#pragma unroll
                for (int j = 0; j < 8; ++j) mma16816(acc[j], pah, bh[j]);
#pragma unroll
                for (int j = 0; j < 8; ++j) mma16816(acc[j], pah, bl[j]);
            }
        }
        if (kt < qt) cp_wait0();
        __syncthreads();
    }

    // epilogue: normalize + fp16, reference layout
    {
        const int row0 = wq*16 + (lane >> 2);
        const float inv0 = 1.0f / l_s[row0];
        const float inv1 = 1.0f / l_s[row0 + 8];
        const int t0 = q0 + row0, t1 = t0 + 8;
        const int rowA = 128*h + (t0 >> 4), rowB2 = 128*h + (t1 >> 4);
        const int cbase0 = ((t0 & 15) << 7), cbase1 = ((t1 & 15) << 7);
#pragma unroll
        for (int j = 0; j < 8; ++j) {
            const int d = wk*64 + j*8 + (lane & 3)*2;
            const size_t i0 = (size_t)(b*T_ + rowA)*C_ + cbase0 + d;
            const size_t i1 = (size_t)(b*T_ + rowB2)*C_ + cbase1 + d;
            *(uint32_t*)&g_att[i0] = pack_h2(__float2half_rn(acc[j][0]*inv0),
                                             __float2half_rn(acc[j][1]*inv0));
            *(uint32_t*)&g_att[i1] = pack_h2(__float2half_rn(acc[j][2]*inv1),
                                             __float2half_rn(acc[j][3]*inv1));
        }
    }
}

// ---------------------------------------------------------------------------
extern "C" void kernel_launch(void* const* d_in, const int* in_sizes, int n_in,
                              void* d_out, int out_size)
{
    const float* x = nullptr; const float* qkv_w = nullptr; const float* out_w = nullptr;
    for (int i = 0; i < n_in; ++i) {
        if      (in_sizes[i] == B_*T_*C_) x     = (const float*)d_in[i];
        else if (in_sizes[i] == 3*C_*C_)  qkv_w = (const float*)d_in[i];
        else if (in_sizes[i] == C_*C_)    out_w = (const float*)d_in[i];
    }
    if (!x)     x     = (const float*)d_in[0];
    if (!qkv_w) qkv_w = (const float*)d_in[1];
    if (!out_w) out_w = (const float*)d_in[2];
    float* out = (float*)d_out;

    float *qkv_ptr;
    __half *x16, *w16, *o16, *att;
    cudaGetSymbolAddress((void**)&qkv_ptr, g_qkv);
    cudaGetSymbolAddress((void**)&x16, g_x16);
    cudaGetSymbolAddress((void**)&w16, g_w16);
    cudaGetSymbolAddress((void**)&o16, g_o16);
    cudaGetSymbolAddress((void**)&att, g_att);

    cudaFuncSetAttribute(tc_gemm, cudaFuncAttributeMaxDynamicSharedMemorySize, TC_SMEM);
    cudaFuncSetAttribute(attn_kernel, cudaFuncAttributeMaxDynamicSharedMemorySize, ATT_SMEM);

    // 1) fp32 -> fp16 conversions
    cvt_half<<<(M_*C_/4 + 255)/256, 256>>>(x, x16, M_*C_/4);
    cvt_half<<<(NQKV_*C_/4 + 255)/256, 256>>>(qkv_w, w16, NQKV_*C_/4);
    cvt_half<<<(C_*C_/4 + 255)/256, 256>>>(out_w, o16, C_*C_/4);
    // 2) QKV projection (HMMA, pure fp16 operands, fp32 accum)
    tc_gemm<<<dim3(NQKV_/128, M_/128), 256, TC_SMEM>>>(x16, w16, qkv_ptr, NQKV_);
    // 3) RoPE + reorganize -> fp16 operands
    rope_reorg<<<(B_*H_*64*(T_/4))/256, 256>>>();
    // 4) HMMA causal flash attention (K,V 2-split; writes g_att)
    attn_kernel<<<dim3(T_/64, H_, B_), 256, ATT_SMEM>>>();
    // 5) Output projection (HMMA, pure fp16 operands)
    tc_gemm<<<dim3(C_/128, M_/128), 256, TC_SMEM>>>(att, o16, out, C_);
}

// round 16
// speedup vs baseline: 2.0639x; 1.2814x over previous
#include <cuda_runtime.h>
#include <cuda_fp16.h>
#include <math.h>
#include <stdint.h>

#define B_ 2
#define T_ 2048
#define C_ 2048
#define H_ 16
#define D_ 128
#define M_ 4096
#define NQKV_ 6144
#define K_ 2048
#define NCHUNK 32      /* K_/64 */

// ---------------- scratch (device globals: allocation-free) ----------------
__device__ float g_qkv[(size_t)M_*NQKV_];
__device__ __half g_x16[(size_t)M_*C_];                              // A of QKV
__device__ __half g_w16[(size_t)NQKV_*C_];                           // B of QKV
__device__ __half g_o16[(size_t)C_*C_];                              // B of out-proj
__device__ __half g_att[(size_t)M_*C_];                              // attn out (A of out-proj)
__device__ __half g_qh[(size_t)B_*H_*T_*D_];                         // Q
__device__ __half g_kh[(size_t)B_*H_*T_*D_];                         // K
__device__ __half g_vth[(size_t)B_*H_*D_*T_];                        // V^T [B,H,D,T]

extern __shared__ __align__(16) char dyn_smem[];

// ---------------- sm_80-class primitives (legal on plain sm_103) -----------
__device__ __forceinline__ uint32_t smem_u32(const void* p) {
    uint32_t a;
    asm("{ .reg .u64 t; cvta.to.shared.u64 t, %1; cvt.u32.u64 %0, t; }"
        : "=r"(a) : "l"(p));
    return a;
}
__device__ __forceinline__ void cp16(uint32_t dst, const void* src) {
    asm volatile("cp.async.cg.shared.global [%0], [%1], 16;"
                 :: "r"(dst), "l"(src) : "memory");
}
__device__ __forceinline__ void cp_commit() {
    asm volatile("cp.async.commit_group;" ::: "memory");
}
__device__ __forceinline__ void cp_wait0() {
    asm volatile("cp.async.wait_group 0;" ::: "memory");
}
__device__ __forceinline__ void cp_wait1() {
    asm volatile("cp.async.wait_group 1;" ::: "memory");
}
__device__ __forceinline__ void ldsm_x4(uint32_t* r, uint32_t addr) {
    asm volatile("ldmatrix.sync.aligned.m8n8.x4.shared.b16 {%0,%1,%2,%3}, [%4];"
                 : "=r"(r[0]), "=r"(r[1]), "=r"(r[2]), "=r"(r[3]) : "r"(addr));
}
__device__ __forceinline__ void mma16816(float* c, const uint32_t* a, const uint32_t* b) {
    asm volatile(
        "mma.sync.aligned.m16n8k16.row.col.f32.f16.f16.f32 "
        "{%0,%1,%2,%3}, {%4,%5,%6,%7}, {%8,%9}, {%0,%1,%2,%3};"
        : "+f"(c[0]), "+f"(c[1]), "+f"(c[2]), "+f"(c[3])
        : "r"(a[0]), "r"(a[1]), "r"(a[2]), "r"(a[3]), "r"(b[0]), "r"(b[1]));
}
// SW128 swizzled address inside a [rows][64 fp16] tile (128B rows)
__device__ __forceinline__ uint32_t swz(uint32_t tile_base, int row, int col2 /*bytes*/) {
    return tile_base + ((uint32_t)row << 7) + ((uint32_t)col2 ^ (((uint32_t)row & 7u) << 4));
}
__device__ __forceinline__ uint32_t pack_h2(__half lo, __half hi) {
    return (uint32_t)__half_as_ushort(lo) | ((uint32_t)__half_as_ushort(hi) << 16);
}

// tile loaders: [64 rows][64 fp16] and [128 rows][64 fp16], SW128 swizzled
__device__ __forceinline__ void tile64_async(uint32_t dst, const __half* src,
                                             size_t pitch, int tid)
{
#pragma unroll
    for (int u = 0; u < 2; ++u) {
        const int c = tid*2 + u;
        const int row = c >> 3, seg = (c & 7) * 16;
        uint32_t o = (uint32_t)(row*128 + seg);
        o ^= ((o >> 3) & 0x70);
        cp16(dst + o, (const char*)(src + (size_t)row*pitch) + seg);
    }
}
__device__ __forceinline__ void tile128_async(uint32_t dst, const __half* src,
                                              size_t pitch, int tid)
{
#pragma unroll
    for (int u = 0; u < 4; ++u) {
        const int c = tid*4 + u;
        const int row = c >> 3, seg = (c & 7) * 16;
        uint32_t o = (uint32_t)(row*128 + seg);
        o ^= ((o >> 3) & 0x70);
        cp16(dst + o, (const char*)(src + (size_t)row*pitch) + seg);
    }
}

// ---------------------------------------------------------------------------
// fp32 -> fp16 conversion.
// ---------------------------------------------------------------------------
__global__ void __launch_bounds__(256)
cvt_half(const float* __restrict__ src, __half* __restrict__ dst, int n4)
{
    const int i = blockIdx.x*256 + threadIdx.x;
    if (i >= n4) return;
    const float4 v = ((const float4*)src)[i];
    ((__half2*)dst)[i*2+0] = __floats2half2_rn(v.x, v.y);
    ((__half2*)dst)[i*2+1] = __floats2half2_rn(v.z, v.w);
}

// ---------------------------------------------------------------------------
// HMMA fp16 NT GEMM: C = A * B^T, fp32 accum. CTA 64(M)x128(N), BK=64,
// 3-stage cp.async, 8 warps (2x4, warp tile 32x32), 2 CTAs/SM.
// ---------------------------------------------------------------------------
#define TCOFF(buf) ((uint32_t)((buf)*24576))   /* stage: A 8K + B 16K */
#define TC_SMEM (3*24576)   /* 72 KB -> 2 CTAs/SM */

__global__ void __launch_bounds__(256, 2)
tc_gemm(const __half* __restrict__ Ah, const __half* __restrict__ Bh,
        float* __restrict__ Cout, int N)
{
    const uint32_t sbase = smem_u32(dyn_smem);
    const int tid = threadIdx.x, wid = tid >> 5, lane = tid & 31;
    const int wy = wid >> 2, wx = wid & 3;          // 2 x 4 warp grid
    const int m0 = blockIdx.y * 64, n0 = blockIdx.x * 128;
    const int r = lane & 7, g = lane >> 3;

    float acc[2][4][4];
#pragma unroll
    for (int i = 0; i < 2; ++i)
#pragma unroll
        for (int j = 0; j < 4; ++j)
#pragma unroll
            for (int e = 0; e < 4; ++e) acc[i][j][e] = 0.0f;

#pragma unroll
    for (int p = 0; p < 2; ++p) {
        tile64_async (sbase + TCOFF(p) + 0,    Ah + (size_t)m0*K_ + p*64, K_, tid);
        tile128_async(sbase + TCOFF(p) + 8192, Bh + (size_t)n0*K_ + p*64, K_, tid);
        cp_commit();
    }

    for (int chunk = 0; chunk < NCHUNK; ++chunk) {
        const uint32_t st = sbase + TCOFF(chunk % 3);
        if (chunk == NCHUNK-1) cp_wait0(); else cp_wait1();
        __syncthreads();
        if (chunk + 2 < NCHUNK) {
            const uint32_t nb = sbase + TCOFF((chunk + 2) % 3);
            const int k0n = (chunk + 2) * 64;
            tile64_async (nb + 0,    Ah + (size_t)m0*K_ + k0n, K_, tid);
            tile128_async(nb + 8192, Bh + (size_t)n0*K_ + k0n, K_, tid);
            cp_commit();
        }
#pragma unroll
        for (int ks = 0; ks < 4; ++ks) {
            uint32_t ah[2][4], bh[4][2];
            const int colA = ks*32 + (g>>1)*16;
            const int colB = ks*32 + (g&1)*16;
#pragma unroll
            for (int i = 0; i < 2; ++i) {
                const int row = wy*32 + i*16 + r + (g&1)*8;
                ldsm_x4(ah[i], swz(st + 0, row, colA));
            }
#pragma unroll
            for (int jj = 0; jj < 2; ++jj) {
                const int row = wx*32 + jj*16 + r + (g>>1)*8;
                uint32_t t[4];
                ldsm_x4(t, swz(st + 8192, row, colB));
                bh[jj*2][0]=t[0]; bh[jj*2][1]=t[1];
                bh[jj*2+1][0]=t[2]; bh[jj*2+1][1]=t[3];
            }
#pragma unroll
            for (int i = 0; i < 2; ++i)
#pragma unroll
                for (int j = 0; j < 4; ++j)
                    mma16816(acc[i][j], ah[i], bh[j]);
        }
    }
#pragma unroll
    for (int i = 0; i < 2; ++i) {
        const int rm = m0 + wy*32 + i*16 + (lane >> 2);
#pragma unroll
        for (int j = 0; j < 4; ++j) {
            const int cn = n0 + wx*32 + j*8 + (lane & 3)*2;
            *(float2*)&Cout[(size_t)rm*N + cn]     = make_float2(acc[i][j][0], acc[i][j][1]);
            *(float2*)&Cout[(size_t)(rm+8)*N + cn] = make_float2(acc[i][j][2], acc[i][j][3]);
        }
    }
}

// ---------------------------------------------------------------------------
// RoPE + reorganize -> fp16: qh, kh [B,H,T,D]; vth [B,H,D,T].
// ---------------------------------------------------------------------------
__global__ void rope_reorg()
{
    const int idx = blockIdx.x * 256 + threadIdx.x;
    const int t4 = idx & 511;
    const int i  = (idx >> 9) & 63;
    const int h  = (idx >> 15) & (H_ - 1);
    const int b  = idx >> 19;
    const int bh = b*H_ + h;
    const int col = h*D_ + i;

    const float mlt = (float)(-9.210340371976184 / 128.0);
    const float div = expf((float)(2*i) * mlt);

#pragma unroll
    for (int u = 0; u < 4; ++u) {
        const int t = t4*4 + u;
        const size_t row = (size_t)(b*T_ + t) * NQKV_;
        const float q1 = g_qkv[row + 0*C_ + col];
        const float q2 = g_qkv[row + 0*C_ + col + 64];
        const float k1 = g_qkv[row + 1*C_ + col];
        const float k2 = g_qkv[row + 1*C_ + col + 64];
        const float v1 = g_qkv[row + 2*C_ + col];
        const float v2 = g_qkv[row + 2*C_ + col + 64];

        float s, c;
        sincosf((float)t * div, &s, &c);

        const size_t off = ((size_t)bh * T_ + t) * D_ + i;
        g_qh[off]      = __float2half_rn(q1*c - q2*s);
        g_qh[off + 64] = __float2half_rn(q2*c + q1*s);
        g_kh[off]      = __float2half_rn(k1*c - k2*s);
        g_kh[off + 64] = __float2half_rn(k2*c + k1*s);
        const size_t koff = ((size_t)bh * D_ + i) * T_ + t;
        g_vth[koff]         = __float2half_rn(v1);
        g_vth[koff + 64*T_] = __float2half_rn(v2);
    }
}

// ---------------------------------------------------------------------------
// HMMA causal flash attention, pure fp16 operands, fp32 softmax/accum.
// 64-q tiles, 8 warps (S: 4x2, PV: 4x2), double-buffered K/V, 2 CTAs/SM.
// smem: Q 16K | KV[2]: kh 16K + vth 16K | Ss 17408 | Ph 8192 | m/l/sc 768
// ---------------------------------------------------------------------------
#define AQ_OFF   0u
#define AKV_OFF(buf) (16384u + (buf)*32768u)
#define ASS_OFF  81920u
#define APH_OFF  99328u
#define AML_OFF  107520u
#define ATT_SMEM 108288

__global__ void __launch_bounds__(256, 2)
attn_kernel()
{
    const uint32_t sb = smem_u32(dyn_smem);
    float* Ss  = (float*)(dyn_smem + ASS_OFF);
    float* m_s = (float*)(dyn_smem + AML_OFF);
    float* l_s = m_s + 64;
    float* sc_s = l_s + 64;

    const int tid = threadIdx.x, wid = tid >> 5, lane = tid & 31;
    const int r = lane & 7, g = lane >> 3;
    const int wq = wid >> 1, wk = wid & 1;
    const int qt = (gridDim.x - 1) - blockIdx.x;
    const int h = blockIdx.y, b = blockIdx.z;
    const size_t hoff  = (size_t)(b*H_ + h) * T_ * D_;
    const size_t hofft = (size_t)(b*H_ + h) * D_ * T_;
    const int q0 = qt * 64;

    tile64_async(sb + AQ_OFF + 0,    g_qh + hoff + (size_t)q0*D_,      D_, tid);
    tile64_async(sb + AQ_OFF + 8192, g_qh + hoff + (size_t)q0*D_ + 64, D_, tid);
    {
        const uint32_t kv = sb + AKV_OFF(0);
        tile64_async (kv + 0,     g_kh + hoff, D_, tid);
        tile64_async (kv + 8192,  g_kh + hoff + 64, D_, tid);
        tile128_async(kv + 16384, g_vth + hofft, T_, tid);
    }
    cp_commit(); cp_wait0();
    if (tid < 64) { m_s[tid] = -INFINITY; l_s[tid] = 0.0f; }
    __syncthreads();

    float acc[8][4];
#pragma unroll
    for (int j = 0; j < 8; ++j)
#pragma unroll
        for (int e = 0; e < 4; ++e) acc[j][e] = 0.0f;

    const float scl = 0.08838834764831845f;
    const int sr = tid >> 2, sq = tid & 3;

    for (int kt = 0; kt <= qt; ++kt) {
        const int buf = kt & 1;
        if (kt < qt) {
            const int k0n = (kt + 1) * 64;
            const uint32_t kv = sb + AKV_OFF(buf^1);
            tile64_async (kv + 0,     g_kh + hoff + (size_t)k0n*D_, D_, tid);
            tile64_async (kv + 8192,  g_kh + hoff + (size_t)k0n*D_ + 64, D_, tid);
            tile128_async(kv + 16384, g_vth + hofft + k0n, T_, tid);
            cp_commit();
        }
        const uint32_t sQH = sb + AQ_OFF;
        const uint32_t sKH = sb + AKV_OFF(buf);
        const uint32_t sVH = sb + AKV_OFF(buf) + 16384;

        // ---- S = Q K^T ----
        {
            float s[4][4];
#pragma unroll
            for (int j = 0; j < 4; ++j)
#pragma unroll
                for (int e = 0; e < 4; ++e) s[j][e] = 0.0f;
#pragma unroll
            for (int ks = 0; ks < 8; ++ks) {
                const uint32_t subo = (uint32_t)(ks >> 2) * 8192u;
                const int colA = (ks & 3)*32 + (g>>1)*16;
                const int colB = (ks & 3)*32 + (g&1)*16;
                uint32_t ah[4], bh[4][2];
                const int rowA = wq*16 + r + (g&1)*8;
                ldsm_x4(ah, swz(sQH + subo, rowA, colA));
#pragma unroll
                for (int jj = 0; jj < 2; ++jj) {
                    const int rowB = wk*32 + jj*16 + r + (g>>1)*8;
                    uint32_t t[4];
                    ldsm_x4(t, swz(sKH + subo, rowB, colB));
                    bh[jj*2][0]=t[0]; bh[jj*2][1]=t[1];
                    bh[jj*2+1][0]=t[2]; bh[jj*2+1][1]=t[3];
                }
#pragma unroll
                for (int j = 0; j < 4; ++j) mma16816(s[j], ah, bh[j]);
            }
#pragma unroll
            for (int j = 0; j < 4; ++j) {
                const int row0 = wq*16 + (lane >> 2);
                const int cc = wk*32 + j*8 + (lane & 3)*2;
                *(float2*)&Ss[row0*68 + cc]     = make_float2(s[j][0]*scl, s[j][1]*scl);
                *(float2*)&Ss[(row0+8)*68 + cc] = make_float2(s[j][2]*scl, s[j][3]*scl);
            }
        }
        __syncthreads();
        // ---- softmax (fp32) + write P (fp16) ----
        {
            const int k0 = kt * 64;
            float* row = Ss + sr*68;
            int kmax = q0 + sr - k0 + 1;
            if (kmax > 64) kmax = 64;
            const float m_old = m_s[sr];
            float mx = m_old;
#pragma unroll
            for (int c0 = 0; c0 < 16; ++c0) {
                const int c = sq*16 + c0;
                if (c < kmax) mx = fmaxf(mx, row[c]);
            }
            mx = fmaxf(mx, __shfl_xor_sync(0xffffffff, mx, 1));
            mx = fmaxf(mx, __shfl_xor_sync(0xffffffff, mx, 2));
            float sum = 0.0f;
#pragma unroll
            for (int cp = 0; cp < 8; ++cp) {
                const int c = sq*16 + cp*2;
                const float p0 = (c   < kmax) ? __expf(row[c]   - mx) : 0.0f;
                const float p1 = (c+1 < kmax) ? __expf(row[c+1] - mx) : 0.0f;
                sum += p0 + p1;
                *(uint32_t*)(dyn_smem + swz(APH_OFF, sr, c*2)) =
                    pack_h2(__float2half_rn(p0), __float2half_rn(p1));
            }
            sum += __shfl_xor_sync(0xffffffff, sum, 1);
            sum += __shfl_xor_sync(0xffffffff, sum, 2);
            if (sq == 0) {
                const float sc = __expf(m_old - mx);
                m_s[sr]  = mx;
                l_s[sr]  = l_s[sr] * sc + sum;
                sc_s[sr] = sc;
            }
        }
        __syncthreads();
        // ---- O = O*sc + P V ----
        {
            const int row0 = wq*16 + (lane >> 2);
            const float sc0 = sc_s[row0], sc1 = sc_s[row0 + 8];
#pragma unroll
            for (int j = 0; j < 8; ++j) {
                acc[j][0] *= sc0; acc[j][1] *= sc0;
                acc[j][2] *= sc1; acc[j][3] *= sc1;
            }
#pragma unroll
            for (int ks = 0; ks < 4; ++ks) {
                const int colA = ks*32 + (g>>1)*16;
                const int colB = ks*32 + (g&1)*16;
                uint32_t pah[4], bh[8][2];
                const int rowA = wq*16 + r + (g&1)*8;
                ldsm_x4(pah, swz(sb + APH_OFF, rowA, colA));
#pragma unroll
                for (int jj = 0; jj < 4; ++jj) {
                    const int rowB = wk*64 + jj*16 + r + (g>>1)*8;
                    uint32_t t[4];
                    ldsm_x4(t, swz(sVH, rowB, colB));
                    bh[jj*2][0]=t[0]; bh[jj*2][1]=t[1];
                    bh[jj*2+1][0]=t[2]; bh[jj*2+1][1]=t[3];
                }
#pragma unroll
                for (int j = 0; j < 8; ++j) mma16816(acc[j], pah, bh[j]);
            }
        }
        if (kt < qt) cp_wait0();
        __syncthreads();
    }

    // epilogue: normalize + fp16, reference layout
    {
        const int row0 = wq*16 + (lane >> 2);
        const float inv0 = 1.0f / l_s[row0];
        const float inv1 = 1.0f / l_s[row0 + 8];
        const int t0 = q0 + row0, t1 = t0 + 8;
        const int rowA = 128*h + (t0 >> 4), rowB2 = 128*h + (t1 >> 4);
        const int cbase0 = ((t0 & 15) << 7), cbase1 = ((t1 & 15) << 7);
#pragma unroll
        for (int j = 0; j < 8; ++j) {
            const int d = wk*64 + j*8 + (lane & 3)*2;
            const size_t i0 = (size_t)(b*T_ + rowA)*C_ + cbase0 + d;
            const size_t i1 = (size_t)(b*T_ + rowB2)*C_ + cbase1 + d;
            *(uint32_t*)&g_att[i0] = pack_h2(__float2half_rn(acc[j][0]*inv0),
                                             __float2half_rn(acc[j][1]*inv0));
            *(uint32_t*)&g_att[i1] = pack_h2(__float2half_rn(acc[j][2]*inv1),
                                             __float2half_rn(acc[j][3]*inv1));
        }
    }
}

// ---------------------------------------------------------------------------
extern "C" void kernel_launch(void* const* d_in, const int* in_sizes, int n_in,
                              void* d_out, int out_size)
{
    const float* x = nullptr; const float* qkv_w = nullptr; const float* out_w = nullptr;
    for (int i = 0; i < n_in; ++i) {
        if      (in_sizes[i] == B_*T_*C_) x     = (const float*)d_in[i];
        else if (in_sizes[i] == 3*C_*C_)  qkv_w = (const float*)d_in[i];
        else if (in_sizes[i] == C_*C_)    out_w = (const float*)d_in[i];
    }
    if (!x)     x     = (const float*)d_in[0];
    if (!qkv_w) qkv_w = (const float*)d_in[1];
    if (!out_w) out_w = (const float*)d_in[2];
    float* out = (float*)d_out;

    float *qkv_ptr;
    __half *x16, *w16, *o16, *att;
    cudaGetSymbolAddress((void**)&qkv_ptr, g_qkv);
    cudaGetSymbolAddress((void**)&x16, g_x16);
    cudaGetSymbolAddress((void**)&w16, g_w16);
    cudaGetSymbolAddress((void**)&o16, g_o16);
    cudaGetSymbolAddress((void**)&att, g_att);

    cudaFuncSetAttribute(tc_gemm, cudaFuncAttributeMaxDynamicSharedMemorySize, TC_SMEM);
    cudaFuncSetAttribute(attn_kernel, cudaFuncAttributeMaxDynamicSharedMemorySize, ATT_SMEM);

    // 1) fp32 -> fp16 conversions
    cvt_half<<<(M_*C_/4 + 255)/256, 256>>>(x, x16, M_*C_/4);
    cvt_half<<<(NQKV_*C_/4 + 255)/256, 256>>>(qkv_w, w16, NQKV_*C_/4);
    cvt_half<<<(C_*C_/4 + 255)/256, 256>>>(out_w, o16, C_*C_/4);
    // 2) QKV projection (HMMA, 2 CTAs/SM)
    tc_gemm<<<dim3(NQKV_/128, M_/64), 256, TC_SMEM>>>(x16, w16, qkv_ptr, NQKV_);
    // 3) RoPE + reorganize -> fp16 operands
    rope_reorg<<<(B_*H_*64*(T_/4))/256, 256>>>();
    // 4) HMMA causal flash attention (2 CTAs/SM; writes g_att)
    attn_kernel<<<dim3(T_/64, H_, B_), 256, ATT_SMEM>>>();
    // 5) Output projection (HMMA, 2 CTAs/SM)
    tc_gemm<<<dim3(C_/128, M_/64), 256, TC_SMEM>>>(att, o16, out, C_);
}

// round 17
// speedup vs baseline: 2.2855x; 1.1073x over previous
#include <cuda_runtime.h>
#include <cuda_fp16.h>
#include <math.h>
#include <stdint.h>

#define B_ 2
#define T_ 2048
#define C_ 2048
#define H_ 16
#define D_ 128
#define M_ 4096
#define NQKV_ 6144
#define K_ 2048
#define NCHUNK 32      /* K_/64 */

// ---------------- scratch (device globals: allocation-free) ----------------
__device__ float g_qkv[(size_t)M_*NQKV_];
__device__ __half g_x16[(size_t)M_*C_];
__device__ __half g_w16[(size_t)NQKV_*C_];
__device__ __half g_o16[(size_t)C_*C_];
__device__ __half g_att[(size_t)M_*C_];
__device__ __half g_qh[(size_t)B_*H_*T_*D_];
__device__ __half g_kh[(size_t)B_*H_*T_*D_];
__device__ __half g_vth[(size_t)B_*H_*D_*T_];   // V^T [B,H,D,T]

extern __shared__ __align__(16) char dyn_smem[];

// ---------------- sm_80-class primitives (legal on plain sm_103) -----------
__device__ __forceinline__ uint32_t smem_u32(const void* p) {
    uint32_t a;
    asm("{ .reg .u64 t; cvta.to.shared.u64 t, %1; cvt.u32.u64 %0, t; }"
        : "=r"(a) : "l"(p));
    return a;
}
__device__ __forceinline__ void cp16(uint32_t dst, const void* src) {
    asm volatile("cp.async.cg.shared.global [%0], [%1], 16;"
                 :: "r"(dst), "l"(src) : "memory");
}
__device__ __forceinline__ void cp_commit() {
    asm volatile("cp.async.commit_group;" ::: "memory");
}
__device__ __forceinline__ void cp_wait0() {
    asm volatile("cp.async.wait_group 0;" ::: "memory");
}
__device__ __forceinline__ void cp_wait1() {
    asm volatile("cp.async.wait_group 1;" ::: "memory");
}
__device__ __forceinline__ void ldsm_x4(uint32_t* r, uint32_t addr) {
    asm volatile("ldmatrix.sync.aligned.m8n8.x4.shared.b16 {%0,%1,%2,%3}, [%4];"
                 : "=r"(r[0]), "=r"(r[1]), "=r"(r[2]), "=r"(r[3]) : "r"(addr));
}
__device__ __forceinline__ void mma16816(float* c, const uint32_t* a, const uint32_t* b) {
    asm volatile(
        "mma.sync.aligned.m16n8k16.row.col.f32.f16.f16.f32 "
        "{%0,%1,%2,%3}, {%4,%5,%6,%7}, {%8,%9}, {%0,%1,%2,%3};"
        : "+f"(c[0]), "+f"(c[1]), "+f"(c[2]), "+f"(c[3])
        : "r"(a[0]), "r"(a[1]), "r"(a[2]), "r"(a[3]), "r"(b[0]), "r"(b[1]));
}
__device__ __forceinline__ uint32_t swz(uint32_t tile_base, int row, int col2) {
    return tile_base + ((uint32_t)row << 7) + ((uint32_t)col2 ^ (((uint32_t)row & 7u) << 4));
}
__device__ __forceinline__ uint32_t pack_h2(__half lo, __half hi) {
    return (uint32_t)__half_as_ushort(lo) | ((uint32_t)__half_as_ushort(hi) << 16);
}

// tile loaders: [64 rows][64 fp16] and [128 rows][64 fp16], SW128 swizzled
__device__ __forceinline__ void tile64_async(uint32_t dst, const __half* src,
                                             size_t pitch, int tid)
{
#pragma unroll
    for (int u = 0; u < 2; ++u) {
        const int c = tid*2 + u;
        const int row = c >> 3, seg = (c & 7) * 16;
        uint32_t o = (uint32_t)(row*128 + seg);
        o ^= ((o >> 3) & 0x70);
        cp16(dst + o, (const char*)(src + (size_t)row*pitch) + seg);
    }
}
__device__ __forceinline__ void tile128_async(uint32_t dst, const __half* src,
                                              size_t pitch, int tid)
{
#pragma unroll
    for (int u = 0; u < 4; ++u) {
        const int c = tid*4 + u;
        const int row = c >> 3, seg = (c & 7) * 16;
        uint32_t o = (uint32_t)(row*128 + seg);
        o ^= ((o >> 3) & 0x70);
        cp16(dst + o, (const char*)(src + (size_t)row*pitch) + seg);
    }
}

// ---------------------------------------------------------------------------
// fp32 -> fp16 conversion.
// ---------------------------------------------------------------------------
__global__ void __launch_bounds__(256)
cvt_half(const float* __restrict__ src, __half* __restrict__ dst, int n4)
{
    const int i = blockIdx.x*256 + threadIdx.x;
    if (i >= n4) return;
    const float4 v = ((const float4*)src)[i];
    ((__half2*)dst)[i*2+0] = __floats2half2_rn(v.x, v.y);
    ((__half2*)dst)[i*2+1] = __floats2half2_rn(v.z, v.w);
}

// ---------------------------------------------------------------------------
// HMMA fp16 NT GEMM (unchanged from R16, passed): CTA 64x128, BK=64,
// 3-stage cp.async, 8 warps, 2 CTAs/SM.
// ---------------------------------------------------------------------------
#define TCOFF(buf) ((uint32_t)((buf)*24576))
#define TC_SMEM (3*24576)   /* 72 KB */

__global__ void __launch_bounds__(256, 2)
tc_gemm(const __half* __restrict__ Ah, const __half* __restrict__ Bh,
        float* __restrict__ Cout, int N)
{
    const uint32_t sbase = smem_u32(dyn_smem);
    const int tid = threadIdx.x, wid = tid >> 5, lane = tid & 31;
    const int wy = wid >> 2, wx = wid & 3;
    const int m0 = blockIdx.y * 64, n0 = blockIdx.x * 128;
    const int r = lane & 7, g = lane >> 3;

    float acc[2][4][4];
#pragma unroll
    for (int i = 0; i < 2; ++i)
#pragma unroll
        for (int j = 0; j < 4; ++j)
#pragma unroll
            for (int e = 0; e < 4; ++e) acc[i][j][e] = 0.0f;

#pragma unroll
    for (int p = 0; p < 2; ++p) {
        tile64_async (sbase + TCOFF(p) + 0,    Ah + (size_t)m0*K_ + p*64, K_, tid);
        tile128_async(sbase + TCOFF(p) + 8192, Bh + (size_t)n0*K_ + p*64, K_, tid);
        cp_commit();
    }

    for (int chunk = 0; chunk < NCHUNK; ++chunk) {
        const uint32_t st = sbase + TCOFF(chunk % 3);
        if (chunk == NCHUNK-1) cp_wait0(); else cp_wait1();
        __syncthreads();
        if (chunk + 2 < NCHUNK) {
            const uint32_t nb = sbase + TCOFF((chunk + 2) % 3);
            const int k0n = (chunk + 2) * 64;
            tile64_async (nb + 0,    Ah + (size_t)m0*K_ + k0n, K_, tid);
            tile128_async(nb + 8192, Bh + (size_t)n0*K_ + k0n, K_, tid);
            cp_commit();
        }
#pragma unroll
        for (int ks = 0; ks < 4; ++ks) {
            uint32_t ah[2][4], bh[4][2];
            const int colA = ks*32 + (g>>1)*16;
            const int colB = ks*32 + (g&1)*16;
#pragma unroll
            for (int i = 0; i < 2; ++i) {
                const int row = wy*32 + i*16 + r + (g&1)*8;
                ldsm_x4(ah[i], swz(st + 0, row, colA));
            }
#pragma unroll
            for (int jj = 0; jj < 2; ++jj) {
                const int row = wx*32 + jj*16 + r + (g>>1)*8;
                uint32_t t[4];
                ldsm_x4(t, swz(st + 8192, row, colB));
                bh[jj*2][0]=t[0]; bh[jj*2][1]=t[1];
                bh[jj*2+1][0]=t[2]; bh[jj*2+1][1]=t[3];
            }
#pragma unroll
            for (int i = 0; i < 2; ++i)
#pragma unroll
                for (int j = 0; j < 4; ++j)
                    mma16816(acc[i][j], ah[i], bh[j]);
        }
    }
#pragma unroll
    for (int i = 0; i < 2; ++i) {
        const int rm = m0 + wy*32 + i*16 + (lane >> 2);
#pragma unroll
        for (int j = 0; j < 4; ++j) {
            const int cn = n0 + wx*32 + j*8 + (lane & 3)*2;
            *(float2*)&Cout[(size_t)rm*N + cn]     = make_float2(acc[i][j][0], acc[i][j][1]);
            *(float2*)&Cout[(size_t)(rm+8)*N + cn] = make_float2(acc[i][j][2], acc[i][j][3]);
        }
    }
}

// ---------------------------------------------------------------------------
// RoPE + reorganize -> fp16 (unchanged from R16).
// ---------------------------------------------------------------------------
__global__ void rope_reorg()
{
    const int idx = blockIdx.x * 256 + threadIdx.x;
    const int t4 = idx & 511;
    const int i  = (idx >> 9) & 63;
    const int h  = (idx >> 15) & (H_ - 1);
    const int b  = idx >> 19;
    const int bh = b*H_ + h;
    const int col = h*D_ + i;

    const float mlt = (float)(-9.210340371976184 / 128.0);
    const float div = expf((float)(2*i) * mlt);

#pragma unroll
    for (int u = 0; u < 4; ++u) {
        const int t = t4*4 + u;
        const size_t row = (size_t)(b*T_ + t) * NQKV_;
        const float q1 = g_qkv[row + 0*C_ + col];
        const float q2 = g_qkv[row + 0*C_ + col + 64];
        const float k1 = g_qkv[row + 1*C_ + col];
        const float k2 = g_qkv[row + 1*C_ + col + 64];
        const float v1 = g_qkv[row + 2*C_ + col];
        const float v2 = g_qkv[row + 2*C_ + col + 64];

        float s, c;
        sincosf((float)t * div, &s, &c);

        const size_t off = ((size_t)bh * T_ + t) * D_ + i;
        g_qh[off]      = __float2half_rn(q1*c - q2*s);
        g_qh[off + 64] = __float2half_rn(q2*c + q1*s);
        g_kh[off]      = __float2half_rn(k1*c - k2*s);
        g_kh[off + 64] = __float2half_rn(k2*c + k1*s);
        const size_t koff = ((size_t)bh * D_ + i) * T_ + t;
        g_vth[koff]         = __float2half_rn(v1);
        g_vth[koff + 64*T_] = __float2half_rn(v2);
    }
}

// ---------------------------------------------------------------------------
// HMMA causal flash attention, FA2-style register softmax.
// 128-q tiles, 8 warps; warp = 16 q-rows x full 64 k. S and P stay in
// registers (c-frag == A-frag repack). 1 barrier per k-tile.
// smem: Q [2x 128x64] 32KB | KV[2]: K 16KB + VT 16KB  => 96KB, 1 CTA/SM.
// ---------------------------------------------------------------------------
#define ATT_SMEM 98304

__global__ void __launch_bounds__(256, 1)
attn_kernel()
{
    const uint32_t sb = smem_u32(dyn_smem);
    const int tid = threadIdx.x, wid = tid >> 5, lane = tid & 31;
    const int r = lane & 7, g = lane >> 3;
    const int qt = (gridDim.x - 1) - blockIdx.x;
    const int h = blockIdx.y, b = blockIdx.z;
    const size_t hoff  = (size_t)(b*H_ + h) * T_ * D_;
    const size_t hofft = (size_t)(b*H_ + h) * D_ * T_;
    const int q0 = qt * 128;

    // Q tile [128][128] as two [128][64] subtiles
    tile128_async(sb + 0,     g_qh + hoff + (size_t)q0*D_,      D_, tid);
    tile128_async(sb + 16384, g_qh + hoff + (size_t)q0*D_ + 64, D_, tid);
    {   // KV tile 0
        const uint32_t kv = sb + 32768;
        tile64_async (kv + 0,     g_kh + hoff,      D_, tid);
        tile64_async (kv + 8192,  g_kh + hoff + 64, D_, tid);
        tile128_async(kv + 16384, g_vth + hofft,    T_, tid);
    }
    cp_commit(); cp_wait0();
    __syncthreads();

    float acc[16][4];
#pragma unroll
    for (int j = 0; j < 16; ++j)
#pragma unroll
        for (int e = 0; e < 4; ++e) acc[j][e] = 0.0f;
    float m0 = -INFINITY, m1 = -INFINITY, l0 = 0.0f, l1 = 0.0f;

    const float scl = 0.08838834764831845f;   // 1/sqrt(128)
    const int rbase = q0 + wid*16;             // warp's first q row (absolute)
    const int trow0 = rbase + (lane >> 2);     // this thread's rows
    const int ntiles = 2*qt + 2;

    for (int kt = 0; kt < ntiles; ++kt) {
        const uint32_t kv = sb + 32768 + (uint32_t)(kt & 1)*32768;
        if (kt + 1 < ntiles) {   // prefetch next KV into other buffer
            const int k0n = (kt + 1) * 64;
            const uint32_t nb = sb + 32768 + (uint32_t)((kt + 1) & 1)*32768;
            tile64_async (nb + 0,     g_kh + hoff + (size_t)k0n*D_,      D_, tid);
            tile64_async (nb + 8192,  g_kh + hoff + (size_t)k0n*D_ + 64, D_, tid);
            tile128_async(nb + 16384, g_vth + hofft + k0n, T_, tid);
            cp_commit();
        }
        const int k0 = kt * 64;
        const bool active = (k0 <= rbase + 15);   // warp-uniform causal skip
        if (active) {
            // ---- S = Q K^T : s[8][4] in registers ----
            float s[8][4];
#pragma unroll
            for (int j = 0; j < 8; ++j)
#pragma unroll
                for (int e = 0; e < 4; ++e) s[j][e] = 0.0f;
#pragma unroll
            for (int ks = 0; ks < 8; ++ks) {
                const uint32_t qsub = sb + (uint32_t)(ks >> 2)*16384u;
                const uint32_t ksub = kv + (uint32_t)(ks >> 2)*8192u;
                const int colA = (ks & 3)*32 + (g>>1)*16;
                const int colB = (ks & 3)*32 + (g&1)*16;
                uint32_t ah[4], bh[8][2];
                ldsm_x4(ah, swz(qsub, wid*16 + r + (g&1)*8, colA));
#pragma unroll
                for (int jj = 0; jj < 4; ++jj) {
                    const int rowB = jj*16 + r + (g>>1)*8;
                    uint32_t t[4];
                    ldsm_x4(t, swz(ksub, rowB, colB));
                    bh[jj*2][0]=t[0]; bh[jj*2][1]=t[1];
                    bh[jj*2+1][0]=t[2]; bh[jj*2+1][1]=t[3];
                }
#pragma unroll
                for (int j = 0; j < 8; ++j) mma16816(s[j], ah, bh[j]);
            }
            // ---- register softmax ----
            const bool need_mask = (k0 + 63 > rbase);   // warp-uniform
            float mx0 = -INFINITY, mx1 = -INFINITY;
#pragma unroll
            for (int j = 0; j < 8; ++j) {
                const int c = k0 + j*8 + (lane & 3)*2;
#pragma unroll
                for (int e = 0; e < 4; ++e) s[j][e] *= scl;
                if (need_mask) {
                    if (c   > trow0) s[j][0] = -INFINITY;
                    if (c+1 > trow0) s[j][1] = -INFINITY;
                    if (c   > trow0+8) s[j][2] = -INFINITY;
                    if (c+1 > trow0+8) s[j][3] = -INFINITY;
                }
                mx0 = fmaxf(mx0, fmaxf(s[j][0], s[j][1]));
                mx1 = fmaxf(mx1, fmaxf(s[j][2], s[j][3]));
            }
            mx0 = fmaxf(mx0, __shfl_xor_sync(0xffffffff, mx0, 1));
            mx0 = fmaxf(mx0, __shfl_xor_sync(0xffffffff, mx0, 2));
            mx1 = fmaxf(mx1, __shfl_xor_sync(0xffffffff, mx1, 1));
            mx1 = fmaxf(mx1, __shfl_xor_sync(0xffffffff, mx1, 2));
            const float mn0 = fmaxf(m0, mx0), mn1 = fmaxf(m1, mx1);
            const float sc0 = __expf(m0 - mn0), sc1 = __expf(m1 - mn1);
            float sum0 = 0.0f, sum1 = 0.0f;
            uint32_t pa[4][4];
#pragma unroll
            for (int j = 0; j < 8; ++j) {
                s[j][0] = __expf(s[j][0] - mn0);
                s[j][1] = __expf(s[j][1] - mn0);
                s[j][2] = __expf(s[j][2] - mn1);
                s[j][3] = __expf(s[j][3] - mn1);
                sum0 += s[j][0] + s[j][1];
                sum1 += s[j][2] + s[j][3];
            }
#pragma unroll
            for (int kc = 0; kc < 4; ++kc) {   // c-frag -> A-frag repack
                pa[kc][0] = pack_h2(__float2half_rn(s[2*kc][0]),   __float2half_rn(s[2*kc][1]));
                pa[kc][1] = pack_h2(__float2half_rn(s[2*kc][2]),   __float2half_rn(s[2*kc][3]));
                pa[kc][2] = pack_h2(__float2half_rn(s[2*kc+1][0]), __float2half_rn(s[2*kc+1][1]));
                pa[kc][3] = pack_h2(__float2half_rn(s[2*kc+1][2]), __float2half_rn(s[2*kc+1][3]));
            }
            sum0 += __shfl_xor_sync(0xffffffff, sum0, 1);
            sum0 += __shfl_xor_sync(0xffffffff, sum0, 2);
            sum1 += __shfl_xor_sync(0xffffffff, sum1, 1);
            sum1 += __shfl_xor_sync(0xffffffff, sum1, 2);
            l0 = l0*sc0 + sum0; m0 = mn0;
            l1 = l1*sc1 + sum1; m1 = mn1;
            // ---- O = O*sc + P V ----
#pragma unroll
            for (int j = 0; j < 16; ++j) {
                acc[j][0] *= sc0; acc[j][1] *= sc0;
                acc[j][2] *= sc1; acc[j][3] *= sc1;
            }
            const uint32_t sVT = kv + 16384;
#pragma unroll
            for (int kc = 0; kc < 4; ++kc) {
                const int colB = kc*32 + (g&1)*16;
#pragma unroll
                for (int hb = 0; hb < 2; ++hb) {   // two batches of 4 ldsm / 8 mma
                    uint32_t vb[8][2];
#pragma unroll
                    for (int jj = 0; jj < 4; ++jj) {
                        const int rowB = (hb*4 + jj)*16 + r + (g>>1)*8;
                        uint32_t t[4];
                        ldsm_x4(t, swz(sVT, rowB, colB));
                        vb[jj*2][0]=t[0]; vb[jj*2][1]=t[1];
                        vb[jj*2+1][0]=t[2]; vb[jj*2+1][1]=t[3];
                    }
#pragma unroll
                    for (int n = 0; n < 8; ++n)
                        mma16816(acc[hb*8 + n], pa[kc], vb[n]);
                }
            }
        }
        if (kt + 1 < ntiles) cp_wait0();
        __syncthreads();
    }

    // epilogue: normalize + fp16, reference layout
    {
        const float inv0 = 1.0f / l0, inv1 = 1.0f / l1;
        const int t0 = trow0, t1 = trow0 + 8;
        const int rowA = 128*h + (t0 >> 4), rowB2 = 128*h + (t1 >> 4);
        const int cbase0 = ((t0 & 15) << 7), cbase1 = ((t1 & 15) << 7);
#pragma unroll
        for (int j = 0; j < 16; ++j) {
            const int d = j*8 + (lane & 3)*2;
            const size_t i0 = (size_t)(b*T_ + rowA)*C_ + cbase0 + d;
            const size_t i1 = (size_t)(b*T_ + rowB2)*C_ + cbase1 + d;
            *(uint32_t*)&g_att[i0] = pack_h2(__float2half_rn(acc[j][0]*inv0),
                                             __float2half_rn(acc[j][1]*inv0));
            *(uint32_t*)&g_att[i1] = pack_h2(__float2half_rn(acc[j][2]*inv1),
                                             __float2half_rn(acc[j][3]*inv1));
        }
    }
}

// ---------------------------------------------------------------------------
extern "C" void kernel_launch(void* const* d_in, const int* in_sizes, int n_in,
                              void* d_out, int out_size)
{
    const float* x = nullptr; const float* qkv_w = nullptr; const float* out_w = nullptr;
    for (int i = 0; i < n_in; ++i) {
        if      (in_sizes[i] == B_*T_*C_) x     = (const float*)d_in[i];
        else if (in_sizes[i] == 3*C_*C_)  qkv_w = (const float*)d_in[i];
        else if (in_sizes[i] == C_*C_)    out_w = (const float*)d_in[i];
    }
    if (!x)     x     = (const float*)d_in[0];
    if (!qkv_w) qkv_w = (const float*)d_in[1];
    if (!out_w) out_w = (const float*)d_in[2];
    float* out = (float*)d_out;

    float *qkv_ptr;
    __half *x16, *w16, *o16, *att;
    cudaGetSymbolAddress((void**)&qkv_ptr, g_qkv);
    cudaGetSymbolAddress((void**)&x16, g_x16);
    cudaGetSymbolAddress((void**)&w16, g_w16);
    cudaGetSymbolAddress((void**)&o16, g_o16);
    cudaGetSymbolAddress((void**)&att, g_att);

    cudaFuncSetAttribute(tc_gemm, cudaFuncAttributeMaxDynamicSharedMemorySize, TC_SMEM);
    cudaFuncSetAttribute(attn_kernel, cudaFuncAttributeMaxDynamicSharedMemorySize, ATT_SMEM);

    // 1) fp32 -> fp16 conversions
    cvt_half<<<(M_*C_/4 + 255)/256, 256>>>(x, x16, M_*C_/4);
    cvt_half<<<(NQKV_*C_/4 + 255)/256, 256>>>(qkv_w, w16, NQKV_*C_/4);
    cvt_half<<<(C_*C_/4 + 255)/256, 256>>>(out_w, o16, C_*C_/4);
    // 2) QKV projection (HMMA, 2 CTAs/SM)
    tc_gemm<<<dim3(NQKV_/128, M_/64), 256, TC_SMEM>>>(x16, w16, qkv_ptr, NQKV_);
    // 3) RoPE + reorganize -> fp16 operands
    rope_reorg<<<(B_*H_*64*(T_/4))/256, 256>>>();
    // 4) HMMA causal flash attention, register softmax (writes g_att)
    attn_kernel<<<dim3(T_/128, H_, B_), 256, ATT_SMEM>>>();
    // 5) Output projection (HMMA, 2 CTAs/SM)
    tc_gemm<<<dim3(C_/128, M_/64), 256, TC_SMEM>>>(att, o16, out, C_);
}